// round 6
// baseline (speedup 1.0000x reference)
#include <cuda_runtime.h>
#include <cuda_bf16.h>
#include <cstdint>

#define BATCH   4
#define T_SEQ   64
#define NSPAT   196
#define CDIM    768
#define HEADS   12
#define HD      64
#define M_TOT   (BATCH * T_SEQ * NSPAT)   // 50176
#define QKV_N   (3 * CDIM)                // 2304

// Scratch (device globals: allocation-free per harness rules)
__device__ float g_qkv[(size_t)M_TOT * QKV_N];   // 462 MB
__device__ float g_att[(size_t)M_TOT * CDIM];    // 154 MB
__device__ float g_xr [(size_t)M_TOT * CDIM];    // tf32-rounded x
__device__ float g_wq [(size_t)QKV_N * CDIM];    // tf32-rounded w_qkv
__device__ float g_wp [(size_t)CDIM * CDIM];     // tf32-rounded w_proj

// ---------------------------------------------------------------------------
// helpers
// ---------------------------------------------------------------------------
__device__ __forceinline__ void cp_async16(uint32_t saddr, const void* gptr) {
    asm volatile("cp.async.cg.shared.global [%0], [%1], 16;\n" :: "r"(saddr), "l"(gptr));
}
__device__ __forceinline__ void cp_commit() {
    asm volatile("cp.async.commit_group;\n" ::: "memory");
}
__device__ __forceinline__ void cp_wait1() {
    asm volatile("cp.async.wait_group 1;\n" ::: "memory");
}
__device__ __forceinline__ float f2tf32(float x) {
    float r;
    asm("cvt.rna.tf32.f32 %0, %1;" : "=f"(r) : "f"(x));
    return r;
}
// D += A*B  (m16n8k8, tf32 bits in registers)
__device__ __forceinline__ void mma1688(float* d, const uint32_t* a, const uint32_t* b) {
    asm volatile(
        "mma.sync.aligned.m16n8k8.row.col.f32.tf32.tf32.f32 "
        "{%0,%1,%2,%3}, {%4,%5,%6,%7}, {%8,%9}, {%0,%1,%2,%3};"
        : "+f"(d[0]), "+f"(d[1]), "+f"(d[2]), "+f"(d[3])
        : "r"(a[0]), "r"(a[1]), "r"(a[2]), "r"(a[3]), "r"(b[0]), "r"(b[1]));
}

// ---------------------------------------------------------------------------
// Raw-PTX TF32 GEMM: C[m][n] = sum_k A[m*K+k] * B[n*K+k] (+ bias[n])
// Block 128(m) x 256(n), BK=32, 3-stage cp.async, 512 threads = 16 warps (4x4),
// warp tile 32x64 = 2(m-frag) x 8(n-frag) of m16n8k8.
// Inputs must be pre-rounded to tf32 (bits fed directly to mma).
// ---------------------------------------------------------------------------
#define GBM 128
#define GBN 256
#define GBK 32
#define G_LDS 36                                // row stride floats (144B)
#define G_STAGE_F ((GBM + GBN) * G_LDS)         // 13,824 floats = 55,296 B
#define G_STAGES 3
#define G_SMEM (G_STAGES * G_STAGE_F * 4)       // 165,888 B

__global__ void __launch_bounds__(512, 1) gemm_mma_kernel(
    const float* __restrict__ A, const float* __restrict__ B,
    float* __restrict__ C, const float* __restrict__ bias,
    int M, int N, int K)
{
    extern __shared__ float smem[];

    const int n0 = blockIdx.x * GBN;     // N fastest -> weights L2-resident
    const int m0 = blockIdx.y * GBM;

    const int tid  = threadIdx.x;
    const int warp = tid >> 5;
    const int lane = tid & 31;
    const int wm   = warp >> 2;          // 0..3 -> rows wm*32
    const int wn   = warp & 3;           // 0..3 -> cols wn*64
    const int g    = lane >> 2;          // 0..7
    const int t    = lane & 3;           // 0..3

    float acc[2][8][4];
    #pragma unroll
    for (int i = 0; i < 2; i++)
        #pragma unroll
        for (int j = 0; j < 8; j++)
            #pragma unroll
            for (int c = 0; c < 4; c++)
                acc[i][j][c] = 0.0f;

    const int NB = K / GBK;

    // stage loader: 3072 float4 chunks (A rows 0..127, B rows 128..383), 6/thread
    auto issue_stage = [&](int kb, int s) {
        float* dst = smem + s * G_STAGE_F;
        #pragma unroll
        for (int i = 0; i < 6; i++) {
            int id = tid + i * 512;              // 0..3071
            int r  = id >> 3;                    // 0..383
            int c  = id & 7;                     // 0..7
            const float* gp = (r < GBM)
                ? A + (size_t)(m0 + r) * K + kb * GBK + c * 4
                : B + (size_t)(n0 + r - GBM) * K + kb * GBK + c * 4;
            uint32_t sa = (uint32_t)__cvta_generic_to_shared(&dst[r * G_LDS + c * 4]);
            cp_async16(sa, gp);
        }
    };

    issue_stage(0, 0); cp_commit();
    issue_stage(1, 1); cp_commit();

    for (int kb = 0; kb < NB; kb++) {
        cp_wait1();            // stage kb resident
        __syncthreads();       // all threads' data visible; prev compute done

        if (kb + 2 < NB) issue_stage(kb + 2, (kb + 2) % 3);
        cp_commit();           // exactly one group per iteration

        const uint32_t* As = (const uint32_t*)(smem + (kb % 3) * G_STAGE_F);
        const uint32_t* Bs = As + GBM * G_LDS;

        #pragma unroll
        for (int k0 = 0; k0 < GBK; k0 += 8) {
            uint32_t a[2][4];
            #pragma unroll
            for (int mf = 0; mf < 2; mf++) {
                int r = (wm * 32 + mf * 16 + g) * G_LDS + k0 + t;
                a[mf][0] = As[r];
                a[mf][1] = As[r + 8 * G_LDS];
                a[mf][2] = As[r + 4];
                a[mf][3] = As[r + 8 * G_LDS + 4];
            }
            uint32_t b[8][2];
            #pragma unroll
            for (int nf = 0; nf < 8; nf++) {
                int r = (wn * 64 + nf * 8 + g) * G_LDS + k0 + t;
                b[nf][0] = Bs[r];
                b[nf][1] = Bs[r + 4];
            }
            #pragma unroll
            for (int mf = 0; mf < 2; mf++)
                #pragma unroll
                for (int nf = 0; nf < 8; nf++)
                    mma1688(acc[mf][nf], a[mf], b[nf]);
        }
    }

    // direct register epilogue, fused bias, float2 stores
    #pragma unroll
    for (int nf = 0; nf < 8; nf++) {
        int col = n0 + wn * 64 + nf * 8 + 2 * t;
        float2 bv = make_float2(0.0f, 0.0f);
        if (bias) bv = *(const float2*)&bias[col];
        #pragma unroll
        for (int mf = 0; mf < 2; mf++) {
            int row = m0 + wm * 32 + mf * 16 + g;
            float2 v0 = make_float2(acc[mf][nf][0] + bv.x, acc[mf][nf][1] + bv.y);
            float2 v1 = make_float2(acc[mf][nf][2] + bv.x, acc[mf][nf][3] + bv.y);
            *(float2*)&C[(size_t)row * N + col]       = v0;
            *(float2*)&C[(size_t)(row + 8) * N + col] = v1;
        }
    }
}

// ---------------------------------------------------------------------------
// tf32 rounding prepass (RN)
// ---------------------------------------------------------------------------
__global__ void __launch_bounds__(256) round_tf32_kernel(
    const float* __restrict__ in, float* __restrict__ out, size_t n4)
{
    size_t i = (size_t)blockIdx.x * 256 + threadIdx.x;
    if (i < n4) {
        float4 v = ((const float4*)in)[i];
        v.x = f2tf32(v.x); v.y = f2tf32(v.y); v.z = f2tf32(v.z); v.w = f2tf32(v.w);
        ((float4*)out)[i] = v;
    }
}

// ---------------------------------------------------------------------------
// Causal attention per (b,h,n): T=64, hd=64. 256 threads, 4x4 per-thread tiles.
// Outputs rounded to tf32 (feed raw-bits GEMM3).
// ---------------------------------------------------------------------------
#define LDT 68

__global__ void __launch_bounds__(256) attn_kernel(
    const float* __restrict__ qkv, float* __restrict__ att)
{
    extern __shared__ float smemf[];
    float* sQ = smemf;
    float* sK = smemf + 64 * LDT;
    float* sV = smemf + 2 * 64 * LDT;
    float* sP = sQ;

    const int blk = blockIdx.x;
    const int n = blk % NSPAT;
    const int h = (blk / NSPAT) % HEADS;
    const int b = blk / (NSPAT * HEADS);

    const int tid = threadIdx.x;
    const size_t rowstride = (size_t)NSPAT * QKV_N;
    const size_t base = ((size_t)b * T_SEQ * NSPAT + n) * QKV_N + (size_t)h * HD;

    for (int idx = tid; idx < 64 * 64; idx += 256) {
        int t = idx >> 6;
        int d = idx & 63;
        size_t gaddr = base + (size_t)t * rowstride;
        sQ[d * LDT + t] = qkv[gaddr + d];
        sK[d * LDT + t] = qkv[gaddr + CDIM + d];
        sV[t * 64 + d]  = qkv[gaddr + 2 * CDIM + d];
    }
    __syncthreads();

    const int ti = tid >> 4;
    const int tj = tid & 15;

    float accS[16];
    #pragma unroll
    for (int i = 0; i < 16; i++) accS[i] = 0.0f;

    #pragma unroll 4
    for (int d = 0; d < 64; d++) {
        float4 a4 = *(const float4*)&sQ[d * LDT + 4 * ti];
        float4 b4 = *(const float4*)&sK[d * LDT + 4 * tj];
        float av[4] = {a4.x, a4.y, a4.z, a4.w};
        float bv[4] = {b4.x, b4.y, b4.z, b4.w};
        #pragma unroll
        for (int ii = 0; ii < 4; ii++)
            #pragma unroll
            for (int jj = 0; jj < 4; jj++)
                accS[ii * 4 + jj] += av[ii] * bv[jj];
    }

    const float scale = 0.125f;
    #pragma unroll
    for (int ii = 0; ii < 4; ii++) {
        int i = 4 * ti + ii;
        float mx = -3.402823466e38f;
        #pragma unroll
        for (int jj = 0; jj < 4; jj++) {
            int j = 4 * tj + jj;
            float s = (j <= i) ? accS[ii * 4 + jj] * scale : -3.402823466e38f;
            accS[ii * 4 + jj] = s;
            mx = fmaxf(mx, s);
        }
        #pragma unroll
        for (int m = 8; m >= 1; m >>= 1)
            mx = fmaxf(mx, __shfl_xor_sync(0xffffffffu, mx, m));
        float sum = 0.0f;
        #pragma unroll
        for (int jj = 0; jj < 4; jj++) {
            float e = __expf(accS[ii * 4 + jj] - mx);
            accS[ii * 4 + jj] = e;
            sum += e;
        }
        #pragma unroll
        for (int m = 8; m >= 1; m >>= 1)
            sum += __shfl_xor_sync(0xffffffffu, sum, m);
        float inv = 1.0f / sum;
        #pragma unroll
        for (int jj = 0; jj < 4; jj++) accS[ii * 4 + jj] *= inv;
    }

    __syncthreads();
    #pragma unroll
    for (int ii = 0; ii < 4; ii++)
        #pragma unroll
        for (int jj = 0; jj < 4; jj++)
            sP[(4 * tj + jj) * LDT + 4 * ti + ii] = accS[ii * 4 + jj];
    __syncthreads();

    float o[16];
    #pragma unroll
    for (int i = 0; i < 16; i++) o[i] = 0.0f;

    #pragma unroll 4
    for (int j = 0; j < 64; j++) {
        float4 p4 = *(const float4*)&sP[j * LDT + 4 * ti];
        float4 v4 = *(const float4*)&sV[j * 64 + 4 * tj];
        float pv[4] = {p4.x, p4.y, p4.z, p4.w};
        float vv[4] = {v4.x, v4.y, v4.z, v4.w};
        #pragma unroll
        for (int ii = 0; ii < 4; ii++)
            #pragma unroll
            for (int jj = 0; jj < 4; jj++)
                o[ii * 4 + jj] += pv[ii] * vv[jj];
    }

    #pragma unroll
    for (int ii = 0; ii < 4; ii++) {
        int i = 4 * ti + ii;
        size_t addr = (((size_t)b * T_SEQ + i) * NSPAT + n) * CDIM + (size_t)h * HD + 4 * tj;
        float4 o4 = make_float4(f2tf32(o[ii * 4 + 0]), f2tf32(o[ii * 4 + 1]),
                                f2tf32(o[ii * 4 + 2]), f2tf32(o[ii * 4 + 3]));
        *(float4*)&att[addr] = o4;
    }
}

// ---------------------------------------------------------------------------
extern "C" void kernel_launch(void* const* d_in, const int* in_sizes, int n_in,
                              void* d_out, int out_size)
{
    const float* x      = (const float*)d_in[0];
    const float* w_qkv  = (const float*)d_in[1];
    const float* w_proj = (const float*)d_in[2];
    const float* b_proj = (const float*)d_in[3];
    float* out = (float*)d_out;

    float *qkv_buf, *att_buf, *xr, *wq, *wp;
    cudaGetSymbolAddress((void**)&qkv_buf, g_qkv);
    cudaGetSymbolAddress((void**)&att_buf, g_att);
    cudaGetSymbolAddress((void**)&xr, g_xr);
    cudaGetSymbolAddress((void**)&wq, g_wq);
    cudaGetSymbolAddress((void**)&wp, g_wp);

    const int attn_smem = 2 * 64 * LDT * 4 + 64 * 64 * 4;  // 51,200 B
    static bool attr_done = false;
    if (!attr_done) {
        cudaFuncSetAttribute(gemm_mma_kernel,
                             cudaFuncAttributeMaxDynamicSharedMemorySize, G_SMEM);
        cudaFuncSetAttribute(attn_kernel,
                             cudaFuncAttributeMaxDynamicSharedMemorySize, attn_smem);
        attr_done = true;
    }

    // 0) tf32 rounding prepasses (x and both weights)
    {
        size_t n4 = (size_t)M_TOT * CDIM / 4;
        round_tf32_kernel<<<(unsigned)((n4 + 255) / 256), 256>>>(x, xr, n4);
        size_t wq4 = (size_t)QKV_N * CDIM / 4;
        round_tf32_kernel<<<(unsigned)((wq4 + 255) / 256), 256>>>(w_qkv, wq, wq4);
        size_t wp4 = (size_t)CDIM * CDIM / 4;
        round_tf32_kernel<<<(unsigned)((wp4 + 255) / 256), 256>>>(w_proj, wp, wp4);
    }
    // 1) QKV GEMM: (50176 x 768) @ (2304 x 768)^T
    {
        dim3 grid(QKV_N / GBN, M_TOT / GBM);   // (9, 392)
        gemm_mma_kernel<<<grid, 512, G_SMEM>>>(xr, wq, qkv_buf, nullptr,
                                               M_TOT, QKV_N, CDIM);
    }
    // 2) Attention
    {
        dim3 grid(BATCH * HEADS * NSPAT);      // 9408
        attn_kernel<<<grid, 256, attn_smem>>>(qkv_buf, att_buf);
    }
    // 3) Projection GEMM + fused bias
    {
        dim3 grid(CDIM / GBN, M_TOT / GBM);    // (3, 392)
        gemm_mma_kernel<<<grid, 512, G_SMEM>>>(att_buf, wp, out, b_proj,
                                               M_TOT, CDIM, CDIM);
    }
}

// round 7
// speedup vs baseline: 1.0621x; 1.0621x over previous
#include <cuda_runtime.h>
#include <cuda_bf16.h>
#include <cstdint>

#define BATCH   4
#define T_SEQ   64
#define NSPAT   196
#define CDIM    768
#define HEADS   12
#define HD      64
#define M_TOT   (BATCH * T_SEQ * NSPAT)   // 50176
#define QKV_N   (3 * CDIM)                // 2304

// Scratch (device globals: allocation-free per harness rules)
__device__ float g_qkv[(size_t)M_TOT * QKV_N];   // 462 MB
__device__ float g_att[(size_t)M_TOT * CDIM];    // 154 MB

// ---------------------------------------------------------------------------
// helpers
// ---------------------------------------------------------------------------
__device__ __forceinline__ void cp_async16(uint32_t saddr, const void* gptr) {
    asm volatile("cp.async.cg.shared.global [%0], [%1], 16;\n" :: "r"(saddr), "l"(gptr));
}
__device__ __forceinline__ void cp_commit() {
    asm volatile("cp.async.commit_group;\n" ::: "memory");
}
__device__ __forceinline__ void cp_wait1() {
    asm volatile("cp.async.wait_group 1;\n" ::: "memory");
}
__device__ __forceinline__ float f2tf32(float x) {
    float r;
    asm("cvt.rna.tf32.f32 %0, %1;" : "=f"(r) : "f"(x));
    return r;
}
__device__ __forceinline__ uint32_t tf32bits(uint32_t v) {
    float r = f2tf32(__uint_as_float(v));
    return __float_as_uint(r);
}
// D += A*B  (m16n8k8, tf32 bits in registers)
__device__ __forceinline__ void mma1688(float* d, const uint32_t* a, const uint32_t* b) {
    asm volatile(
        "mma.sync.aligned.m16n8k8.row.col.f32.tf32.tf32.f32 "
        "{%0,%1,%2,%3}, {%4,%5,%6,%7}, {%8,%9}, {%0,%1,%2,%3};"
        : "+f"(d[0]), "+f"(d[1]), "+f"(d[2]), "+f"(d[3])
        : "r"(a[0]), "r"(a[1]), "r"(a[2]), "r"(a[3]), "r"(b[0]), "r"(b[1]));
}

// ---------------------------------------------------------------------------
// Raw-PTX TF32 GEMM: C[m][n] = sum_k A[m*K+k] * B[n*K+k] (+ bias[n])
// Block 128(m) x 256(n), BK=32, 3-stage cp.async, 256 threads = 8 warps (2x4),
// warp tile 64x64 = 4(m-frag) x 8(n-frag) of m16n8k8.
// fp32 inputs; tf32 RNA rounding applied in-register before mma.
// ---------------------------------------------------------------------------
#define GBM 128
#define GBN 256
#define GBK 32
#define G_LDS 36                                // row stride floats (144B)
#define G_STAGE_F ((GBM + GBN) * G_LDS)         // 13,824 floats = 55,296 B
#define G_STAGES 3
#define G_SMEM (G_STAGES * G_STAGE_F * 4)       // 165,888 B

__global__ void __launch_bounds__(256, 1) gemm_mma_kernel(
    const float* __restrict__ A, const float* __restrict__ B,
    float* __restrict__ C, const float* __restrict__ bias,
    int M, int N, int K)
{
    extern __shared__ float smem[];

    const int n0 = blockIdx.x * GBN;     // N fastest -> weights L2-resident
    const int m0 = blockIdx.y * GBM;

    const int tid  = threadIdx.x;
    const int warp = tid >> 5;
    const int lane = tid & 31;
    const int wm   = warp >> 2;          // 0..1 -> rows wm*64
    const int wn   = warp & 3;           // 0..3 -> cols wn*64
    const int g    = lane >> 2;          // 0..7
    const int t    = lane & 3;           // 0..3

    float acc[4][8][4];
    #pragma unroll
    for (int i = 0; i < 4; i++)
        #pragma unroll
        for (int j = 0; j < 8; j++)
            #pragma unroll
            for (int c = 0; c < 4; c++)
                acc[i][j][c] = 0.0f;

    const int NB = K / GBK;

    // stage loader: 3072 float4 chunks (A rows 0..127, B rows 128..383)
    auto issue_stage = [&](int kb, int s) {
        float* dst = smem + s * G_STAGE_F;
        #pragma unroll
        for (int i = 0; i < 12; i++) {
            int id = tid + i * 256;              // 0..3071
            int r  = id >> 3;                    // 0..383
            int c  = id & 7;                     // 0..7
            const float* gp = (r < GBM)
                ? A + (size_t)(m0 + r) * K + kb * GBK + c * 4
                : B + (size_t)(n0 + r - GBM) * K + kb * GBK + c * 4;
            uint32_t sa = (uint32_t)__cvta_generic_to_shared(&dst[r * G_LDS + c * 4]);
            cp_async16(sa, gp);
        }
    };

    issue_stage(0, 0); cp_commit();
    issue_stage(1, 1); cp_commit();

    for (int kb = 0; kb < NB; kb++) {
        cp_wait1();            // stage kb resident
        __syncthreads();       // all threads' data visible; prev compute done

        if (kb + 2 < NB) issue_stage(kb + 2, (kb + 2) % 3);
        cp_commit();           // exactly one group per iteration

        const uint32_t* As = (const uint32_t*)(smem + (kb % 3) * G_STAGE_F);
        const uint32_t* Bs = As + GBM * G_LDS;

        #pragma unroll
        for (int k0 = 0; k0 < GBK; k0 += 8) {
            uint32_t a[4][4];
            #pragma unroll
            for (int mf = 0; mf < 4; mf++) {
                int r = (wm * 64 + mf * 16 + g) * G_LDS + k0 + t;
                a[mf][0] = tf32bits(As[r]);
                a[mf][1] = tf32bits(As[r + 8 * G_LDS]);
                a[mf][2] = tf32bits(As[r + 4]);
                a[mf][3] = tf32bits(As[r + 8 * G_LDS + 4]);
            }
            uint32_t b[8][2];
            #pragma unroll
            for (int nf = 0; nf < 8; nf++) {
                int r = (wn * 64 + nf * 8 + g) * G_LDS + k0 + t;
                b[nf][0] = tf32bits(Bs[r]);
                b[nf][1] = tf32bits(Bs[r + 4]);
            }
            #pragma unroll
            for (int mf = 0; mf < 4; mf++)
                #pragma unroll
                for (int nf = 0; nf < 8; nf++)
                    mma1688(acc[mf][nf], a[mf], b[nf]);
        }
    }

    // direct register epilogue, fused bias, float2 stores
    #pragma unroll
    for (int nf = 0; nf < 8; nf++) {
        int col = n0 + wn * 64 + nf * 8 + 2 * t;
        float2 bv = make_float2(0.0f, 0.0f);
        if (bias) bv = *(const float2*)&bias[col];
        #pragma unroll
        for (int mf = 0; mf < 4; mf++) {
            int row = m0 + wm * 64 + mf * 16 + g;
            float2 v0 = make_float2(acc[mf][nf][0] + bv.x, acc[mf][nf][1] + bv.y);
            float2 v1 = make_float2(acc[mf][nf][2] + bv.x, acc[mf][nf][3] + bv.y);
            *(float2*)&C[(size_t)row * N + col]       = v0;
            *(float2*)&C[(size_t)(row + 8) * N + col] = v1;
        }
    }
}

// ---------------------------------------------------------------------------
// MMA-based causal attention per (b,h,n): T=64, hd=64.
// 128 threads = 4 warps; warp w owns query rows 16w..16w+15.
// S = Q K^T and O = P V via m16n8k8 tf32; softmax in accumulator layout.
// ---------------------------------------------------------------------------
#define ALDT 68
#define ATTN_SMEM (3 * 64 * ALDT * 4)   // 52,224 B

__global__ void __launch_bounds__(128) attn_mma_kernel(
    const float* __restrict__ qkv, float* __restrict__ att)
{
    extern __shared__ float sm[];
    float* sQ  = sm;                 // [q][d] row-major, stride ALDT; reused as sP [q][j]
    float* sK  = sm + 64 * ALDT;     // [key][d]
    float* sVt = sm + 2 * 64 * ALDT; // [d][key]  (V transposed)

    const int blk = blockIdx.x;      // n + NSPAT*(h + HEADS*b)
    const int n = blk % NSPAT;
    const int h = (blk / NSPAT) % HEADS;
    const int b = blk / (NSPAT * HEADS);

    const int tid  = threadIdx.x;
    const int warp = tid >> 5;
    const int lane = tid & 31;
    const int g    = lane >> 2;      // 0..7
    const int t    = lane & 3;       // 0..3

    const size_t rowstride = (size_t)NSPAT * QKV_N;
    const size_t base = ((size_t)b * T_SEQ * NSPAT + n) * QKV_N + (size_t)h * HD;

    // load + tf32-round Q,K,V into smem
    for (int idx = tid; idx < 64 * 64; idx += 128) {
        int tt = idx >> 6;           // token 0..63
        int d  = idx & 63;           // dim 0..63
        size_t gaddr = base + (size_t)tt * rowstride;
        sQ [tt * ALDT + d]  = f2tf32(qkv[gaddr + d]);
        sK [tt * ALDT + d]  = f2tf32(qkv[gaddr + CDIM + d]);
        sVt[d * ALDT + tt]  = f2tf32(qkv[gaddr + 2 * CDIM + d]);
    }
    __syncthreads();

    const int m0 = warp * 16;        // this warp's query rows
    const int i0 = m0 + g;
    const int i1 = m0 + g + 8;

    // ---- S = Q @ K^T (warp tile 16x64) ----
    float s[8][4];
    #pragma unroll
    for (int nf = 0; nf < 8; nf++)
        #pragma unroll
        for (int c = 0; c < 4; c++) s[nf][c] = 0.0f;

    {
        const uint32_t* Qs = (const uint32_t*)sQ;
        const uint32_t* Ks = (const uint32_t*)sK;
        #pragma unroll
        for (int k0 = 0; k0 < 64; k0 += 8) {
            uint32_t a[4];
            int r = i0 * ALDT + k0 + t;
            a[0] = Qs[r];
            a[1] = Qs[r + 8 * ALDT];
            a[2] = Qs[r + 4];
            a[3] = Qs[r + 8 * ALDT + 4];
            #pragma unroll
            for (int nf = 0; nf < 8; nf++) {
                uint32_t bb[2];
                int rb = (nf * 8 + g) * ALDT + k0 + t;
                bb[0] = Ks[rb];
                bb[1] = Ks[rb + 4];
                mma1688(s[nf], a, bb);
            }
        }
    }

    // ---- scale + causal mask + softmax (rows i0 and i1) ----
    const float scale = 0.125f;      // hd^-0.5
    float mx0 = -1e30f, mx1 = -1e30f;
    #pragma unroll
    for (int nf = 0; nf < 8; nf++) {
        int j0 = nf * 8 + 2 * t, j1 = j0 + 1;
        s[nf][0] = (j0 <= i0) ? s[nf][0] * scale : -1e30f;
        s[nf][1] = (j1 <= i0) ? s[nf][1] * scale : -1e30f;
        s[nf][2] = (j0 <= i1) ? s[nf][2] * scale : -1e30f;
        s[nf][3] = (j1 <= i1) ? s[nf][3] * scale : -1e30f;
        mx0 = fmaxf(mx0, fmaxf(s[nf][0], s[nf][1]));
        mx1 = fmaxf(mx1, fmaxf(s[nf][2], s[nf][3]));
    }
    mx0 = fmaxf(mx0, __shfl_xor_sync(0xffffffffu, mx0, 1));
    mx0 = fmaxf(mx0, __shfl_xor_sync(0xffffffffu, mx0, 2));
    mx1 = fmaxf(mx1, __shfl_xor_sync(0xffffffffu, mx1, 1));
    mx1 = fmaxf(mx1, __shfl_xor_sync(0xffffffffu, mx1, 2));

    float sum0 = 0.0f, sum1 = 0.0f;
    #pragma unroll
    for (int nf = 0; nf < 8; nf++) {
        s[nf][0] = __expf(s[nf][0] - mx0);
        s[nf][1] = __expf(s[nf][1] - mx0);
        s[nf][2] = __expf(s[nf][2] - mx1);
        s[nf][3] = __expf(s[nf][3] - mx1);
        sum0 += s[nf][0] + s[nf][1];
        sum1 += s[nf][2] + s[nf][3];
    }
    sum0 += __shfl_xor_sync(0xffffffffu, sum0, 1);
    sum0 += __shfl_xor_sync(0xffffffffu, sum0, 2);
    sum1 += __shfl_xor_sync(0xffffffffu, sum1, 1);
    sum1 += __shfl_xor_sync(0xffffffffu, sum1, 2);
    const float inv0 = 1.0f / sum0;
    const float inv1 = 1.0f / sum1;

    // ---- stage P (tf32-rounded) into sP (overlays sQ; rows are warp-private) ----
    __syncwarp();
    float* sP = sQ;
    #pragma unroll
    for (int nf = 0; nf < 8; nf++) {
        int jc = nf * 8 + 2 * t;
        *(float2*)&sP[i0 * ALDT + jc] =
            make_float2(f2tf32(s[nf][0] * inv0), f2tf32(s[nf][1] * inv0));
        *(float2*)&sP[i1 * ALDT + jc] =
            make_float2(f2tf32(s[nf][2] * inv1), f2tf32(s[nf][3] * inv1));
    }
    __syncwarp();

    // ---- O = P @ V  (warp tile 16x64) ----
    float o[8][4];
    #pragma unroll
    for (int nf = 0; nf < 8; nf++)
        #pragma unroll
        for (int c = 0; c < 4; c++) o[nf][c] = 0.0f;

    {
        const uint32_t* Ps = (const uint32_t*)sP;
        const uint32_t* Vs = (const uint32_t*)sVt;
        #pragma unroll
        for (int k0 = 0; k0 < 64; k0 += 8) {
            uint32_t a[4];
            int r = i0 * ALDT + k0 + t;
            a[0] = Ps[r];
            a[1] = Ps[r + 8 * ALDT];
            a[2] = Ps[r + 4];
            a[3] = Ps[r + 8 * ALDT + 4];
            #pragma unroll
            for (int nf = 0; nf < 8; nf++) {
                uint32_t bb[2];
                int rb = (nf * 8 + g) * ALDT + k0 + t;
                bb[0] = Vs[rb];
                bb[1] = Vs[rb + 4];
                mma1688(o[nf], a, bb);
            }
        }
    }

    // ---- store O: out layout (B, T, N, C) with head offset ----
    #pragma unroll
    for (int nf = 0; nf < 8; nf++) {
        int col = nf * 8 + 2 * t;
        size_t a0 = (((size_t)b * T_SEQ + i0) * NSPAT + n) * CDIM + (size_t)h * HD + col;
        size_t a1 = (((size_t)b * T_SEQ + i1) * NSPAT + n) * CDIM + (size_t)h * HD + col;
        *(float2*)&att[a0] = make_float2(o[nf][0], o[nf][1]);
        *(float2*)&att[a1] = make_float2(o[nf][2], o[nf][3]);
    }
}

// ---------------------------------------------------------------------------
extern "C" void kernel_launch(void* const* d_in, const int* in_sizes, int n_in,
                              void* d_out, int out_size)
{
    const float* x      = (const float*)d_in[0];
    const float* w_qkv  = (const float*)d_in[1];
    const float* w_proj = (const float*)d_in[2];
    const float* b_proj = (const float*)d_in[3];
    float* out = (float*)d_out;

    float *qkv_buf, *att_buf;
    cudaGetSymbolAddress((void**)&qkv_buf, g_qkv);
    cudaGetSymbolAddress((void**)&att_buf, g_att);

    static bool attr_done = false;
    if (!attr_done) {
        cudaFuncSetAttribute(gemm_mma_kernel,
                             cudaFuncAttributeMaxDynamicSharedMemorySize, G_SMEM);
        cudaFuncSetAttribute(attn_mma_kernel,
                             cudaFuncAttributeMaxDynamicSharedMemorySize, ATTN_SMEM);
        attr_done = true;
    }

    // 1) QKV GEMM: (50176 x 768) @ (2304 x 768)^T   (tf32 cvt in-loop)
    {
        dim3 grid(QKV_N / GBN, M_TOT / GBM);   // (9, 392)
        gemm_mma_kernel<<<grid, 256, G_SMEM>>>(x, w_qkv, qkv_buf, nullptr,
                                               M_TOT, QKV_N, CDIM);
    }
    // 2) Attention (tensor-core)
    {
        dim3 grid(BATCH * HEADS * NSPAT);      // 9408
        attn_mma_kernel<<<grid, 128, ATTN_SMEM>>>(qkv_buf, att_buf);
    }
    // 3) Projection GEMM + fused bias
    {
        dim3 grid(CDIM / GBN, M_TOT / GBM);    // (3, 392)
        gemm_mma_kernel<<<grid, 256, G_SMEM>>>(att_buf, w_proj, out, b_proj,
                                               M_TOT, CDIM, CDIM);
    }
}

// round 8
// speedup vs baseline: 1.1346x; 1.0683x over previous
#include <cuda_runtime.h>
#include <cuda_bf16.h>
#include <cstdint>

#define BATCH   4
#define T_SEQ   64
#define NSPAT   196
#define CDIM    768
#define HEADS   12
#define HD      64
#define M_TOT   (BATCH * T_SEQ * NSPAT)   // 50176
#define QKV_N   (3 * CDIM)                // 2304

// Scratch (device globals: allocation-free per harness rules)
__device__ float g_qkv[(size_t)M_TOT * QKV_N];   // 462 MB
__device__ float g_att[(size_t)M_TOT * CDIM];    // 154 MB
__device__ float g_xr [(size_t)M_TOT * CDIM];    // tf32-rounded x
__device__ float g_wq [(size_t)QKV_N * CDIM];    // tf32-rounded w_qkv
__device__ float g_wp [(size_t)CDIM * CDIM];     // tf32-rounded w_proj

// ---------------------------------------------------------------------------
// helpers
// ---------------------------------------------------------------------------
__device__ __forceinline__ void cp_async16(uint32_t saddr, const void* gptr) {
    asm volatile("cp.async.cg.shared.global [%0], [%1], 16;\n" :: "r"(saddr), "l"(gptr));
}
__device__ __forceinline__ void cp_commit() {
    asm volatile("cp.async.commit_group;\n" ::: "memory");
}
__device__ __forceinline__ void cp_wait1() {
    asm volatile("cp.async.wait_group 1;\n" ::: "memory");
}
__device__ __forceinline__ float f2tf32(float x) {
    float r;
    asm("cvt.rna.tf32.f32 %0, %1;" : "=f"(r) : "f"(x));
    return r;
}
// D += A*B  (m16n8k8, tf32 bits in registers)
__device__ __forceinline__ void mma1688(float* d, const uint32_t* a, const uint32_t* b) {
    asm volatile(
        "mma.sync.aligned.m16n8k8.row.col.f32.tf32.tf32.f32 "
        "{%0,%1,%2,%3}, {%4,%5,%6,%7}, {%8,%9}, {%0,%1,%2,%3};"
        : "+f"(d[0]), "+f"(d[1]), "+f"(d[2]), "+f"(d[3])
        : "r"(a[0]), "r"(a[1]), "r"(a[2]), "r"(a[3]), "r"(b[0]), "r"(b[1]));
}

// ---------------------------------------------------------------------------
// Raw-PTX TF32 GEMM: C[m][n] = sum_k A[m*K+k] * B[n*K+k] (+ bias[n])
// Block 128(m) x 256(n), BK=64, 2-stage cp.async, 256 threads = 8 warps (2x4),
// warp tile 64x64; fragments double-buffered across k-steps.
// Inputs must be pre-rounded to tf32.
// ---------------------------------------------------------------------------
#define GBM 128
#define GBN 256
#define GBK 64
#define G_LDS 68                                 // row stride floats (272B)
#define G_STAGE_F ((GBM + GBN) * G_LDS)          // 26,112 floats = 104,448 B
#define G_STAGES 2
#define G_SMEM (G_STAGES * G_STAGE_F * 4)        // 208,896 B

__global__ void __launch_bounds__(256, 1) gemm_mma_kernel(
    const float* __restrict__ A, const float* __restrict__ B,
    float* __restrict__ C, const float* __restrict__ bias,
    int M, int N, int K)
{
    extern __shared__ float smem[];

    const int n0 = blockIdx.x * GBN;     // N fastest -> weights L2-resident
    const int m0 = blockIdx.y * GBM;

    const int tid  = threadIdx.x;
    const int warp = tid >> 5;
    const int lane = tid & 31;
    const int wm   = warp >> 2;          // 0..1 -> rows wm*64
    const int wn   = warp & 3;           // 0..3 -> cols wn*64
    const int g    = lane >> 2;          // 0..7
    const int t    = lane & 3;           // 0..3

    float acc[4][8][4];
    #pragma unroll
    for (int i = 0; i < 4; i++)
        #pragma unroll
        for (int j = 0; j < 8; j++)
            #pragma unroll
            for (int c = 0; c < 4; c++)
                acc[i][j][c] = 0.0f;

    const int NB = K / GBK;              // 12

    // stage loader: 384 rows x 16 float4 = 6144 chunks, 24 per thread
    auto issue_stage = [&](int kb, int s) {
        float* dst = smem + s * G_STAGE_F;
        #pragma unroll
        for (int i = 0; i < 24; i++) {
            int id = tid + i * 256;              // 0..6143
            int r  = id >> 4;                    // 0..383
            int c  = id & 15;                    // 0..15
            const float* gp = (r < GBM)
                ? A + (size_t)(m0 + r) * K + kb * GBK + c * 4
                : B + (size_t)(n0 + r - GBM) * K + kb * GBK + c * 4;
            uint32_t sa = (uint32_t)__cvta_generic_to_shared(&dst[r * G_LDS + c * 4]);
            cp_async16(sa, gp);
        }
    };

    // fragment loaders (k0 = k-step offset within stage, 0..56 step 8)
    auto load_a = [&](const uint32_t* As, int k0, uint32_t a[4][4]) {
        #pragma unroll
        for (int mf = 0; mf < 4; mf++) {
            int r = (wm * 64 + mf * 16 + g) * G_LDS + k0 + t;
            a[mf][0] = As[r];
            a[mf][1] = As[r + 8 * G_LDS];
            a[mf][2] = As[r + 4];
            a[mf][3] = As[r + 8 * G_LDS + 4];
        }
    };
    auto load_b = [&](const uint32_t* Bs, int k0, uint32_t b[8][2]) {
        #pragma unroll
        for (int nf = 0; nf < 8; nf++) {
            int r = (wn * 64 + nf * 8 + g) * G_LDS + k0 + t;
            b[nf][0] = Bs[r];
            b[nf][1] = Bs[r + 4];
        }
    };

    issue_stage(0, 0); cp_commit();
    issue_stage(1, 1); cp_commit();

    for (int kb = 0; kb < NB; kb++) {
        cp_wait1();            // stage kb resident
        __syncthreads();

        const uint32_t* As = (const uint32_t*)(smem + (kb & 1) * G_STAGE_F);
        const uint32_t* Bs = As + GBM * G_LDS;

        uint32_t a0[4][4], b0[8][2], a1[4][4], b1[8][2];
        load_a(As, 0, a0); load_b(Bs, 0, b0);

        #pragma unroll
        for (int ks = 0; ks < 8; ks += 2) {
            // prefetch ks+1 into buf1 while buf0 MMAs issue
            if (ks + 1 < 8) { load_a(As, (ks + 1) * 8, a1); load_b(Bs, (ks + 1) * 8, b1); }
            #pragma unroll
            for (int mf = 0; mf < 4; mf++)
                #pragma unroll
                for (int nf = 0; nf < 8; nf++)
                    mma1688(acc[mf][nf], a0[mf], b0[nf]);
            // prefetch ks+2 into buf0 while buf1 MMAs issue
            if (ks + 2 < 8) { load_a(As, (ks + 2) * 8, a0); load_b(Bs, (ks + 2) * 8, b0); }
            if (ks + 1 < 8) {
                #pragma unroll
                for (int mf = 0; mf < 4; mf++)
                    #pragma unroll
                    for (int nf = 0; nf < 8; nf++)
                        mma1688(acc[mf][nf], a1[mf], b1[nf]);
            }
        }

        __syncthreads();       // all reads of slot kb&1 done before refill
        if (kb + 2 < NB) issue_stage(kb + 2, kb & 1);
        cp_commit();           // one group per iteration
    }

    // direct register epilogue, fused bias, float2 stores
    #pragma unroll
    for (int nf = 0; nf < 8; nf++) {
        int col = n0 + wn * 64 + nf * 8 + 2 * t;
        float2 bv = make_float2(0.0f, 0.0f);
        if (bias) bv = *(const float2*)&bias[col];
        #pragma unroll
        for (int mf = 0; mf < 4; mf++) {
            int row = m0 + wm * 64 + mf * 16 + g;
            float2 v0 = make_float2(acc[mf][nf][0] + bv.x, acc[mf][nf][1] + bv.y);
            float2 v1 = make_float2(acc[mf][nf][2] + bv.x, acc[mf][nf][3] + bv.y);
            *(float2*)&C[(size_t)row * N + col]       = v0;
            *(float2*)&C[(size_t)(row + 8) * N + col] = v1;
        }
    }
}

// ---------------------------------------------------------------------------
// tf32 rounding prepass (RNA)
// ---------------------------------------------------------------------------
__global__ void __launch_bounds__(256) round_tf32_kernel(
    const float* __restrict__ in, float* __restrict__ out, size_t n4)
{
    size_t i = (size_t)blockIdx.x * 256 + threadIdx.x;
    if (i < n4) {
        float4 v = ((const float4*)in)[i];
        v.x = f2tf32(v.x); v.y = f2tf32(v.y); v.z = f2tf32(v.z); v.w = f2tf32(v.w);
        ((float4*)out)[i] = v;
    }
}

// ---------------------------------------------------------------------------
// MMA-based causal attention per (b,h,n): T=64, hd=64.
// 128 threads = 4 warps; warp w owns query rows 16w..16w+15.
// ---------------------------------------------------------------------------
#define ALDT 68
#define ATTN_SMEM (3 * 64 * ALDT * 4)   // 52,224 B

__global__ void __launch_bounds__(128) attn_mma_kernel(
    const float* __restrict__ qkv, float* __restrict__ att)
{
    extern __shared__ float sm[];
    float* sQ  = sm;                 // [q][d], stride ALDT; reused as sP
    float* sK  = sm + 64 * ALDT;     // [key][d]
    float* sVt = sm + 2 * 64 * ALDT; // [d][key]

    const int blk = blockIdx.x;
    const int n = blk % NSPAT;
    const int h = (blk / NSPAT) % HEADS;
    const int b = blk / (NSPAT * HEADS);

    const int tid  = threadIdx.x;
    const int warp = tid >> 5;
    const int lane = tid & 31;
    const int g    = lane >> 2;
    const int t    = lane & 3;

    const size_t rowstride = (size_t)NSPAT * QKV_N;
    const size_t base = ((size_t)b * T_SEQ * NSPAT + n) * QKV_N + (size_t)h * HD;

    for (int idx = tid; idx < 64 * 64; idx += 128) {
        int tt = idx >> 6;
        int d  = idx & 63;
        size_t gaddr = base + (size_t)tt * rowstride;
        sQ [tt * ALDT + d] = f2tf32(qkv[gaddr + d]);
        sK [tt * ALDT + d] = f2tf32(qkv[gaddr + CDIM + d]);
        sVt[d * ALDT + tt] = f2tf32(qkv[gaddr + 2 * CDIM + d]);
    }
    __syncthreads();

    const int m0 = warp * 16;
    const int i0 = m0 + g;
    const int i1 = m0 + g + 8;

    float s[8][4];
    #pragma unroll
    for (int nf = 0; nf < 8; nf++)
        #pragma unroll
        for (int c = 0; c < 4; c++) s[nf][c] = 0.0f;

    {
        const uint32_t* Qs = (const uint32_t*)sQ;
        const uint32_t* Ks = (const uint32_t*)sK;
        #pragma unroll
        for (int k0 = 0; k0 < 64; k0 += 8) {
            uint32_t a[4];
            int r = i0 * ALDT + k0 + t;
            a[0] = Qs[r];
            a[1] = Qs[r + 8 * ALDT];
            a[2] = Qs[r + 4];
            a[3] = Qs[r + 8 * ALDT + 4];
            #pragma unroll
            for (int nf = 0; nf < 8; nf++) {
                uint32_t bb[2];
                int rb = (nf * 8 + g) * ALDT + k0 + t;
                bb[0] = Ks[rb];
                bb[1] = Ks[rb + 4];
                mma1688(s[nf], a, bb);
            }
        }
    }

    const float scale = 0.125f;
    float mx0 = -1e30f, mx1 = -1e30f;
    #pragma unroll
    for (int nf = 0; nf < 8; nf++) {
        int j0 = nf * 8 + 2 * t, j1 = j0 + 1;
        s[nf][0] = (j0 <= i0) ? s[nf][0] * scale : -1e30f;
        s[nf][1] = (j1 <= i0) ? s[nf][1] * scale : -1e30f;
        s[nf][2] = (j0 <= i1) ? s[nf][2] * scale : -1e30f;
        s[nf][3] = (j1 <= i1) ? s[nf][3] * scale : -1e30f;
        mx0 = fmaxf(mx0, fmaxf(s[nf][0], s[nf][1]));
        mx1 = fmaxf(mx1, fmaxf(s[nf][2], s[nf][3]));
    }
    mx0 = fmaxf(mx0, __shfl_xor_sync(0xffffffffu, mx0, 1));
    mx0 = fmaxf(mx0, __shfl_xor_sync(0xffffffffu, mx0, 2));
    mx1 = fmaxf(mx1, __shfl_xor_sync(0xffffffffu, mx1, 1));
    mx1 = fmaxf(mx1, __shfl_xor_sync(0xffffffffu, mx1, 2));

    float sum0 = 0.0f, sum1 = 0.0f;
    #pragma unroll
    for (int nf = 0; nf < 8; nf++) {
        s[nf][0] = __expf(s[nf][0] - mx0);
        s[nf][1] = __expf(s[nf][1] - mx0);
        s[nf][2] = __expf(s[nf][2] - mx1);
        s[nf][3] = __expf(s[nf][3] - mx1);
        sum0 += s[nf][0] + s[nf][1];
        sum1 += s[nf][2] + s[nf][3];
    }
    sum0 += __shfl_xor_sync(0xffffffffu, sum0, 1);
    sum0 += __shfl_xor_sync(0xffffffffu, sum0, 2);
    sum1 += __shfl_xor_sync(0xffffffffu, sum1, 1);
    sum1 += __shfl_xor_sync(0xffffffffu, sum1, 2);
    const float inv0 = 1.0f / sum0;
    const float inv1 = 1.0f / sum1;

    __syncwarp();
    float* sP = sQ;
    #pragma unroll
    for (int nf = 0; nf < 8; nf++) {
        int jc = nf * 8 + 2 * t;
        *(float2*)&sP[i0 * ALDT + jc] =
            make_float2(f2tf32(s[nf][0] * inv0), f2tf32(s[nf][1] * inv0));
        *(float2*)&sP[i1 * ALDT + jc] =
            make_float2(f2tf32(s[nf][2] * inv1), f2tf32(s[nf][3] * inv1));
    }
    __syncwarp();

    float o[8][4];
    #pragma unroll
    for (int nf = 0; nf < 8; nf++)
        #pragma unroll
        for (int c = 0; c < 4; c++) o[nf][c] = 0.0f;

    {
        const uint32_t* Ps = (const uint32_t*)sP;
        const uint32_t* Vs = (const uint32_t*)sVt;
        #pragma unroll
        for (int k0 = 0; k0 < 64; k0 += 8) {
            uint32_t a[4];
            int r = i0 * ALDT + k0 + t;
            a[0] = Ps[r];
            a[1] = Ps[r + 8 * ALDT];
            a[2] = Ps[r + 4];
            a[3] = Ps[r + 8 * ALDT + 4];
            #pragma unroll
            for (int nf = 0; nf < 8; nf++) {
                uint32_t bb[2];
                int rb = (nf * 8 + g) * ALDT + k0 + t;
                bb[0] = Vs[rb];
                bb[1] = Vs[rb + 4];
                mma1688(o[nf], a, bb);
            }
        }
    }

    #pragma unroll
    for (int nf = 0; nf < 8; nf++) {
        int col = nf * 8 + 2 * t;
        size_t a0 = (((size_t)b * T_SEQ + i0) * NSPAT + n) * CDIM + (size_t)h * HD + col;
        size_t a1 = (((size_t)b * T_SEQ + i1) * NSPAT + n) * CDIM + (size_t)h * HD + col;
        // round O to tf32 so GEMM3 needs no A-side rounding
        *(float2*)&att[a0] = make_float2(f2tf32(o[nf][0]), f2tf32(o[nf][1]));
        *(float2*)&att[a1] = make_float2(f2tf32(o[nf][2]), f2tf32(o[nf][3]));
    }
}

// ---------------------------------------------------------------------------
extern "C" void kernel_launch(void* const* d_in, const int* in_sizes, int n_in,
                              void* d_out, int out_size)
{
    const float* x      = (const float*)d_in[0];
    const float* w_qkv  = (const float*)d_in[1];
    const float* w_proj = (const float*)d_in[2];
    const float* b_proj = (const float*)d_in[3];
    float* out = (float*)d_out;

    float *qkv_buf, *att_buf, *xr, *wq, *wp;
    cudaGetSymbolAddress((void**)&qkv_buf, g_qkv);
    cudaGetSymbolAddress((void**)&att_buf, g_att);
    cudaGetSymbolAddress((void**)&xr, g_xr);
    cudaGetSymbolAddress((void**)&wq, g_wq);
    cudaGetSymbolAddress((void**)&wp, g_wp);

    static bool attr_done = false;
    if (!attr_done) {
        cudaFuncSetAttribute(gemm_mma_kernel,
                             cudaFuncAttributeMaxDynamicSharedMemorySize, G_SMEM);
        cudaFuncSetAttribute(attn_mma_kernel,
                             cudaFuncAttributeMaxDynamicSharedMemorySize, ATTN_SMEM);
        attr_done = true;
    }

    // 0) tf32 rounding prepasses
    {
        size_t n4 = (size_t)M_TOT * CDIM / 4;
        round_tf32_kernel<<<(unsigned)((n4 + 255) / 256), 256>>>(x, xr, n4);
        size_t wq4 = (size_t)QKV_N * CDIM / 4;
        round_tf32_kernel<<<(unsigned)((wq4 + 255) / 256), 256>>>(w_qkv, wq, wq4);
        size_t wp4 = (size_t)CDIM * CDIM / 4;
        round_tf32_kernel<<<(unsigned)((wp4 + 255) / 256), 256>>>(w_proj, wp, wp4);
    }
    // 1) QKV GEMM: (50176 x 768) @ (2304 x 768)^T
    {
        dim3 grid(QKV_N / GBN, M_TOT / GBM);   // (9, 392)
        gemm_mma_kernel<<<grid, 256, G_SMEM>>>(xr, wq, qkv_buf, nullptr,
                                               M_TOT, QKV_N, CDIM);
    }
    // 2) Attention (tensor-core)
    {
        dim3 grid(BATCH * HEADS * NSPAT);      // 9408
        attn_mma_kernel<<<grid, 128, ATTN_SMEM>>>(qkv_buf, att_buf);
    }
    // 3) Projection GEMM + fused bias (att_buf already tf32-rounded)
    {
        dim3 grid(CDIM / GBN, M_TOT / GBM);    // (3, 392)
        gemm_mma_kernel<<<grid, 256, G_SMEM>>>(att_buf, wp, out, b_proj,
                                               M_TOT, CDIM, CDIM);
    }
}

// round 9
// speedup vs baseline: 1.9325x; 1.7032x over previous
#include <cuda_runtime.h>
#include <cuda_fp16.h>
#include <cstdint>

#define BATCH   4
#define T_SEQ   64
#define NSPAT   196
#define CDIM    768
#define HEADS   12
#define HD      64
#define M_TOT   (BATCH * T_SEQ * NSPAT)   // 50176
#define QKV_N   (3 * CDIM)                // 2304

// Scratch (device globals: allocation-free per harness rules)
__device__ __half g_qkv[(size_t)M_TOT * QKV_N];  // 231 MB
__device__ __half g_att[(size_t)M_TOT * CDIM];   // 77 MB
__device__ __half g_xh [(size_t)M_TOT * CDIM];   // 77 MB  (fp16 x)
__device__ __half g_wqh[(size_t)QKV_N * CDIM];   // fp16 w_qkv
__device__ __half g_wph[(size_t)CDIM * CDIM];    // fp16 w_proj

// ---------------------------------------------------------------------------
// helpers
// ---------------------------------------------------------------------------
__device__ __forceinline__ void cp_async16(uint32_t saddr, const void* gptr) {
    asm volatile("cp.async.cg.shared.global [%0], [%1], 16;\n" :: "r"(saddr), "l"(gptr));
}
__device__ __forceinline__ void cp_commit() {
    asm volatile("cp.async.commit_group;\n" ::: "memory");
}
__device__ __forceinline__ void cp_wait1() {
    asm volatile("cp.async.wait_group 1;\n" ::: "memory");
}
// D += A*B  (m16n8k16 fp16 inputs, fp32 accum)
__device__ __forceinline__ void mma16816(float* d, const uint32_t* a, const uint32_t* b) {
    asm volatile(
        "mma.sync.aligned.m16n8k16.row.col.f32.f16.f16.f32 "
        "{%0,%1,%2,%3}, {%4,%5,%6,%7}, {%8,%9}, {%0,%1,%2,%3};"
        : "+f"(d[0]), "+f"(d[1]), "+f"(d[2]), "+f"(d[3])
        : "r"(a[0]), "r"(a[1]), "r"(a[2]), "r"(a[3]), "r"(b[0]), "r"(b[1]));
}

// ---------------------------------------------------------------------------
// FP16 MMA GEMM: C[m][n] = sum_k A[m*K+k] * B[n*K+k] (+ bias[n])
// Block 128(m) x 256(n), BK=64, 3-stage cp.async, 256 threads = 8 warps (2x4),
// warp tile 64x64 = 4(m) x 8(n) frags of m16n8k16; frags double-buffered.
// ---------------------------------------------------------------------------
#define GBM 128
#define GBN 256
#define GBK 64
#define G_LDSH 72                                // halves per smem row (144B)
#define G_LDSW 36                                // words per smem row
#define STAGE_BYTES ((GBM + GBN) * G_LDSH * 2)   // 55,296 B
#define G_STAGES 3
#define G_SMEM (G_STAGES * STAGE_BYTES)          // 165,888 B

template<bool HALF_OUT>
__global__ void __launch_bounds__(256, 1) gemm_h_kernel(
    const __half* __restrict__ A, const __half* __restrict__ B,
    void* __restrict__ Cv, const float* __restrict__ bias,
    int M, int N, int K)
{
    extern __shared__ char smem[];

    const int n0 = blockIdx.x * GBN;     // N fastest -> weights L2-resident
    const int m0 = blockIdx.y * GBM;

    const int tid  = threadIdx.x;
    const int warp = tid >> 5;
    const int lane = tid & 31;
    const int wm   = warp >> 2;          // 0..1 -> rows wm*64
    const int wn   = warp & 3;           // 0..3 -> cols wn*64
    const int g    = lane >> 2;          // 0..7
    const int t    = lane & 3;           // 0..3

    float acc[4][8][4];
    #pragma unroll
    for (int i = 0; i < 4; i++)
        #pragma unroll
        for (int j = 0; j < 8; j++)
            #pragma unroll
            for (int c = 0; c < 4; c++)
                acc[i][j][c] = 0.0f;

    const int NB = K / GBK;              // 12

    // stage loader: 384 rows x 8 chunks(16B) = 3072, 12 per thread
    auto issue_stage = [&](int kb, int s) {
        char* dst = smem + s * STAGE_BYTES;
        #pragma unroll
        for (int i = 0; i < 12; i++) {
            int id = tid + i * 256;              // 0..3071
            int r  = id >> 3;                    // 0..383
            int c  = id & 7;                     // 0..7 (8 halves each)
            const __half* gp = (r < GBM)
                ? A + (size_t)(m0 + r) * K + kb * GBK + c * 8
                : B + (size_t)(n0 + r - GBM) * K + kb * GBK + c * 8;
            uint32_t sa = (uint32_t)__cvta_generic_to_shared(dst + r * (G_LDSH * 2) + c * 16);
            cp_async16(sa, gp);
        }
    };

    // fragment loaders; ks = k16-step within stage (0..3)
    auto load_a = [&](const uint32_t* As, int ks, uint32_t a[4][4]) {
        #pragma unroll
        for (int mf = 0; mf < 4; mf++) {
            int w = (wm * 64 + mf * 16 + g) * G_LDSW + ks * 8 + t;
            a[mf][0] = As[w];                    // row g,   k lo
            a[mf][1] = As[w + 8 * G_LDSW];       // row g+8, k lo
            a[mf][2] = As[w + 4];                // row g,   k hi
            a[mf][3] = As[w + 8 * G_LDSW + 4];   // row g+8, k hi
        }
    };
    auto load_b = [&](const uint32_t* Bs, int ks, uint32_t b[8][2]) {
        #pragma unroll
        for (int nf = 0; nf < 8; nf++) {
            int w = (wn * 64 + nf * 8 + g) * G_LDSW + ks * 8 + t;
            b[nf][0] = Bs[w];
            b[nf][1] = Bs[w + 4];
        }
    };

    issue_stage(0, 0); cp_commit();
    issue_stage(1, 1); cp_commit();

    for (int kb = 0; kb < NB; kb++) {
        cp_wait1();            // stage kb resident
        __syncthreads();

        if (kb + 2 < NB) issue_stage(kb + 2, (kb + 2) % 3);
        cp_commit();           // one group per iteration

        const uint32_t* As = (const uint32_t*)(smem + (kb % 3) * STAGE_BYTES);
        const uint32_t* Bs = As + GBM * G_LDSW;

        uint32_t a0[4][4], b0[8][2], a1[4][4], b1[8][2];
        load_a(As, 0, a0); load_b(Bs, 0, b0);

        #pragma unroll
        for (int ks = 0; ks < 4; ks += 2) {
            if (ks + 1 < 4) { load_a(As, ks + 1, a1); load_b(Bs, ks + 1, b1); }
            #pragma unroll
            for (int mf = 0; mf < 4; mf++)
                #pragma unroll
                for (int nf = 0; nf < 8; nf++)
                    mma16816(acc[mf][nf], a0[mf], b0[nf]);
            if (ks + 2 < 4) { load_a(As, ks + 2, a0); load_b(Bs, ks + 2, b0); }
            if (ks + 1 < 4) {
                #pragma unroll
                for (int mf = 0; mf < 4; mf++)
                    #pragma unroll
                    for (int nf = 0; nf < 8; nf++)
                        mma16816(acc[mf][nf], a1[mf], b1[nf]);
            }
        }
        __syncthreads();       // reads of slot kb%3 done before its refill next iters
    }

    // epilogue: fused bias; half2 or float2 stores
    #pragma unroll
    for (int nf = 0; nf < 8; nf++) {
        int col = n0 + wn * 64 + nf * 8 + 2 * t;
        float bx = 0.0f, by = 0.0f;
        if (bias) { float2 bv = *(const float2*)&bias[col]; bx = bv.x; by = bv.y; }
        #pragma unroll
        for (int mf = 0; mf < 4; mf++) {
            int row = m0 + wm * 64 + mf * 16 + g;
            if (HALF_OUT) {
                __half* Ch = (__half*)Cv;
                *(__half2*)&Ch[(size_t)row * N + col] =
                    __floats2half2_rn(acc[mf][nf][0] + bx, acc[mf][nf][1] + by);
                *(__half2*)&Ch[(size_t)(row + 8) * N + col] =
                    __floats2half2_rn(acc[mf][nf][2] + bx, acc[mf][nf][3] + by);
            } else {
                float* Cf = (float*)Cv;
                *(float2*)&Cf[(size_t)row * N + col] =
                    make_float2(acc[mf][nf][0] + bx, acc[mf][nf][1] + by);
                *(float2*)&Cf[(size_t)(row + 8) * N + col] =
                    make_float2(acc[mf][nf][2] + bx, acc[mf][nf][3] + by);
            }
        }
    }
}

// ---------------------------------------------------------------------------
// fp32 -> fp16 conversion prepass
// ---------------------------------------------------------------------------
__global__ void __launch_bounds__(256) f2h_kernel(
    const float* __restrict__ in, __half* __restrict__ out, size_t n4)
{
    size_t i = (size_t)blockIdx.x * 256 + threadIdx.x;
    if (i < n4) {
        float4 v = ((const float4*)in)[i];
        ((__half2*)out)[2 * i + 0] = __floats2half2_rn(v.x, v.y);
        ((__half2*)out)[2 * i + 1] = __floats2half2_rn(v.z, v.w);
    }
}

// ---------------------------------------------------------------------------
// FP16 MMA causal attention per (b,h,n): T=64, hd=64.
// 128 threads = 4 warps; warp w owns query rows 16w..16w+15.
// S = Q K^T, O = P V via m16n8k16; softmax in fp32 accumulator layout.
// ---------------------------------------------------------------------------
#define ALDH 72                       // halves per smem row
#define ALDW 36                       // words per row
#define ATTN_SMEM (3 * 64 * ALDH * 2) // 27,648 B

__global__ void __launch_bounds__(128) attn_mma_kernel(
    const __half* __restrict__ qkv, __half* __restrict__ att)
{
    extern __shared__ char smc[];
    __half* sQ  = (__half*)smc;              // [q][d]; reused as sP [q][j]
    __half* sK  = sQ + 64 * ALDH;            // [key][d]
    __half* sVt = sQ + 2 * 64 * ALDH;        // [d][key]

    const int blk = blockIdx.x;
    const int n = blk % NSPAT;
    const int h = (blk / NSPAT) % HEADS;
    const int b = blk / (NSPAT * HEADS);

    const int tid  = threadIdx.x;
    const int warp = tid >> 5;
    const int lane = tid & 31;
    const int g    = lane >> 2;
    const int t    = lane & 3;

    const size_t rowstride = (size_t)NSPAT * QKV_N;
    const size_t base = ((size_t)b * T_SEQ * NSPAT + n) * QKV_N + (size_t)h * HD;

    // load Q,K,V (half2 loads); V transposed into sVt
    for (int idx = tid; idx < 64 * 32; idx += 128) {
        int tt = idx >> 5;               // token 0..63
        int d2 = idx & 31;               // half2 index 0..31
        const __half2* gp = (const __half2*)(qkv + base + (size_t)tt * rowstride);
        __half2 q2 = gp[d2];
        __half2 k2 = ((const __half2*)(qkv + base + (size_t)tt * rowstride + CDIM))[d2];
        __half2 v2 = ((const __half2*)(qkv + base + (size_t)tt * rowstride + 2 * CDIM))[d2];
        *(__half2*)&sQ[tt * ALDH + 2 * d2] = q2;
        *(__half2*)&sK[tt * ALDH + 2 * d2] = k2;
        sVt[(2 * d2 + 0) * ALDH + tt] = __low2half(v2);
        sVt[(2 * d2 + 1) * ALDH + tt] = __high2half(v2);
    }
    __syncthreads();

    const int m0 = warp * 16;
    const int i0 = m0 + g;
    const int i1 = m0 + g + 8;

    // ---- S = Q @ K^T ----
    float s[8][4];
    #pragma unroll
    for (int nf = 0; nf < 8; nf++)
        #pragma unroll
        for (int c = 0; c < 4; c++) s[nf][c] = 0.0f;

    {
        const uint32_t* Qw = (const uint32_t*)sQ;
        const uint32_t* Kw = (const uint32_t*)sK;
        #pragma unroll
        for (int ks = 0; ks < 4; ks++) {
            uint32_t a[4];
            int w = i0 * ALDW + ks * 8 + t;
            a[0] = Qw[w];
            a[1] = Qw[w + 8 * ALDW];
            a[2] = Qw[w + 4];
            a[3] = Qw[w + 8 * ALDW + 4];
            #pragma unroll
            for (int nf = 0; nf < 8; nf++) {
                uint32_t bb[2];
                int wb = (nf * 8 + g) * ALDW + ks * 8 + t;
                bb[0] = Kw[wb];
                bb[1] = Kw[wb + 4];
                mma16816(s[nf], a, bb);
            }
        }
    }

    // ---- scale + causal mask + softmax (rows i0, i1) ----
    const float scale = 0.125f;
    float mx0 = -1e30f, mx1 = -1e30f;
    #pragma unroll
    for (int nf = 0; nf < 8; nf++) {
        int j0 = nf * 8 + 2 * t, j1 = j0 + 1;
        s[nf][0] = (j0 <= i0) ? s[nf][0] * scale : -1e30f;
        s[nf][1] = (j1 <= i0) ? s[nf][1] * scale : -1e30f;
        s[nf][2] = (j0 <= i1) ? s[nf][2] * scale : -1e30f;
        s[nf][3] = (j1 <= i1) ? s[nf][3] * scale : -1e30f;
        mx0 = fmaxf(mx0, fmaxf(s[nf][0], s[nf][1]));
        mx1 = fmaxf(mx1, fmaxf(s[nf][2], s[nf][3]));
    }
    mx0 = fmaxf(mx0, __shfl_xor_sync(0xffffffffu, mx0, 1));
    mx0 = fmaxf(mx0, __shfl_xor_sync(0xffffffffu, mx0, 2));
    mx1 = fmaxf(mx1, __shfl_xor_sync(0xffffffffu, mx1, 1));
    mx1 = fmaxf(mx1, __shfl_xor_sync(0xffffffffu, mx1, 2));

    float sum0 = 0.0f, sum1 = 0.0f;
    #pragma unroll
    for (int nf = 0; nf < 8; nf++) {
        s[nf][0] = __expf(s[nf][0] - mx0);
        s[nf][1] = __expf(s[nf][1] - mx0);
        s[nf][2] = __expf(s[nf][2] - mx1);
        s[nf][3] = __expf(s[nf][3] - mx1);
        sum0 += s[nf][0] + s[nf][1];
        sum1 += s[nf][2] + s[nf][3];
    }
    sum0 += __shfl_xor_sync(0xffffffffu, sum0, 1);
    sum0 += __shfl_xor_sync(0xffffffffu, sum0, 2);
    sum1 += __shfl_xor_sync(0xffffffffu, sum1, 1);
    sum1 += __shfl_xor_sync(0xffffffffu, sum1, 2);
    const float inv0 = 1.0f / sum0;
    const float inv1 = 1.0f / sum1;

    // ---- stage P (fp16) into sP (overlays sQ; rows warp-private) ----
    __syncwarp();
    __half* sP = sQ;
    #pragma unroll
    for (int nf = 0; nf < 8; nf++) {
        int jc = nf * 8 + 2 * t;
        *(__half2*)&sP[i0 * ALDH + jc] = __floats2half2_rn(s[nf][0] * inv0, s[nf][1] * inv0);
        *(__half2*)&sP[i1 * ALDH + jc] = __floats2half2_rn(s[nf][2] * inv1, s[nf][3] * inv1);
    }
    __syncwarp();

    // ---- O = P @ V ----
    float o[8][4];
    #pragma unroll
    for (int nf = 0; nf < 8; nf++)
        #pragma unroll
        for (int c = 0; c < 4; c++) o[nf][c] = 0.0f;

    {
        const uint32_t* Pw = (const uint32_t*)sP;
        const uint32_t* Vw = (const uint32_t*)sVt;
        #pragma unroll
        for (int ks = 0; ks < 4; ks++) {
            uint32_t a[4];
            int w = i0 * ALDW + ks * 8 + t;
            a[0] = Pw[w];
            a[1] = Pw[w + 8 * ALDW];
            a[2] = Pw[w + 4];
            a[3] = Pw[w + 8 * ALDW + 4];
            #pragma unroll
            for (int nf = 0; nf < 8; nf++) {
                uint32_t bb[2];
                int wb = (nf * 8 + g) * ALDW + ks * 8 + t;
                bb[0] = Vw[wb];
                bb[1] = Vw[wb + 4];
                mma16816(o[nf], a, bb);
            }
        }
    }

    // ---- store O (fp16) ----
    #pragma unroll
    for (int nf = 0; nf < 8; nf++) {
        int col = nf * 8 + 2 * t;
        size_t a0 = (((size_t)b * T_SEQ + i0) * NSPAT + n) * CDIM + (size_t)h * HD + col;
        size_t a1 = (((size_t)b * T_SEQ + i1) * NSPAT + n) * CDIM + (size_t)h * HD + col;
        *(__half2*)&att[a0] = __floats2half2_rn(o[nf][0], o[nf][1]);
        *(__half2*)&att[a1] = __floats2half2_rn(o[nf][2], o[nf][3]);
    }
}

// ---------------------------------------------------------------------------
extern "C" void kernel_launch(void* const* d_in, const int* in_sizes, int n_in,
                              void* d_out, int out_size)
{
    const float* x      = (const float*)d_in[0];
    const float* w_qkv  = (const float*)d_in[1];
    const float* w_proj = (const float*)d_in[2];
    const float* b_proj = (const float*)d_in[3];
    float* out = (float*)d_out;

    __half *qkv_buf, *att_buf, *xh, *wqh, *wph;
    cudaGetSymbolAddress((void**)&qkv_buf, g_qkv);
    cudaGetSymbolAddress((void**)&att_buf, g_att);
    cudaGetSymbolAddress((void**)&xh, g_xh);
    cudaGetSymbolAddress((void**)&wqh, g_wqh);
    cudaGetSymbolAddress((void**)&wph, g_wph);

    static bool attr_done = false;
    if (!attr_done) {
        cudaFuncSetAttribute(gemm_h_kernel<true>,
                             cudaFuncAttributeMaxDynamicSharedMemorySize, G_SMEM);
        cudaFuncSetAttribute(gemm_h_kernel<false>,
                             cudaFuncAttributeMaxDynamicSharedMemorySize, G_SMEM);
        cudaFuncSetAttribute(attn_mma_kernel,
                             cudaFuncAttributeMaxDynamicSharedMemorySize, ATTN_SMEM);
        attr_done = true;
    }

    // 0) fp16 conversion prepasses
    {
        size_t n4 = (size_t)M_TOT * CDIM / 4;
        f2h_kernel<<<(unsigned)((n4 + 255) / 256), 256>>>(x, xh, n4);
        size_t wq4 = (size_t)QKV_N * CDIM / 4;
        f2h_kernel<<<(unsigned)((wq4 + 255) / 256), 256>>>(w_qkv, wqh, wq4);
        size_t wp4 = (size_t)CDIM * CDIM / 4;
        f2h_kernel<<<(unsigned)((wp4 + 255) / 256), 256>>>(w_proj, wph, wp4);
    }
    // 1) QKV GEMM (fp16 in, fp16 out): (50176 x 768) @ (2304 x 768)^T
    {
        dim3 grid(QKV_N / GBN, M_TOT / GBM);   // (9, 392)
        gemm_h_kernel<true><<<grid, 256, G_SMEM>>>(xh, wqh, (void*)qkv_buf, nullptr,
                                                   M_TOT, QKV_N, CDIM);
    }
    // 2) Attention (fp16 tensor-core)
    {
        dim3 grid(BATCH * HEADS * NSPAT);      // 9408
        attn_mma_kernel<<<grid, 128, ATTN_SMEM>>>(qkv_buf, att_buf);
    }
    // 3) Projection GEMM + fused bias (fp16 in, fp32 out)
    {
        dim3 grid(CDIM / GBN, M_TOT / GBM);    // (3, 392)
        gemm_h_kernel<false><<<grid, 256, G_SMEM>>>(att_buf, wph, (void*)out, b_proj,
                                                    M_TOT, CDIM, CDIM);
    }
}

// round 10
// speedup vs baseline: 2.0491x; 1.0603x over previous
#include <cuda_runtime.h>
#include <cuda_fp16.h>
#include <cstdint>

#define BATCH   4
#define T_SEQ   64
#define NSPAT   196
#define CDIM    768
#define HEADS   12
#define HD      64
#define M_TOT   (BATCH * T_SEQ * NSPAT)   // 50176
#define QKV_N   (3 * CDIM)                // 2304

// Scratch (device globals: allocation-free per harness rules)
__device__ __half g_qkv[(size_t)M_TOT * QKV_N];  // 231 MB
__device__ __half g_att[(size_t)M_TOT * CDIM];   // 77 MB
__device__ __half g_xh [(size_t)M_TOT * CDIM];   // 77 MB  (fp16 x)
__device__ __half g_wqh[(size_t)QKV_N * CDIM];   // fp16 w_qkv
__device__ __half g_wph[(size_t)CDIM * CDIM];    // fp16 w_proj

// ---------------------------------------------------------------------------
// helpers
// ---------------------------------------------------------------------------
__device__ __forceinline__ void cp_async16(uint32_t saddr, const void* gptr) {
    asm volatile("cp.async.cg.shared.global [%0], [%1], 16;\n" :: "r"(saddr), "l"(gptr));
}
__device__ __forceinline__ void cp_commit() {
    asm volatile("cp.async.commit_group;\n" ::: "memory");
}
__device__ __forceinline__ void cp_wait1() {
    asm volatile("cp.async.wait_group 1;\n" ::: "memory");
}
// D += A*B  (m16n8k16 fp16 inputs, fp32 accum)
__device__ __forceinline__ void mma16816(float* d, const uint32_t* a, const uint32_t* b) {
    asm volatile(
        "mma.sync.aligned.m16n8k16.row.col.f32.f16.f16.f32 "
        "{%0,%1,%2,%3}, {%4,%5,%6,%7}, {%8,%9}, {%0,%1,%2,%3};"
        : "+f"(d[0]), "+f"(d[1]), "+f"(d[2]), "+f"(d[3])
        : "r"(a[0]), "r"(a[1]), "r"(a[2]), "r"(a[3]), "r"(b[0]), "r"(b[1]));
}

// ---------------------------------------------------------------------------
// FP16 MMA GEMM: C[m][n] = sum_k A[m*K+k] * B[n*K+k] (+ bias[n])
// Block 128(m) x 128(n), BK=64, 3-stage cp.async, 128 threads = 4 warps (2x2),
// warp tile 64x64 = 4(m) x 8(n) frags of m16n8k16; frags double-buffered.
// 2 CTAs co-resident per SM -> independent sync domains hide barrier bubbles.
// ---------------------------------------------------------------------------
#define GBM 128
#define GBN 128
#define GBK 64
#define G_LDSH 72                                // halves per smem row (144B)
#define G_LDSW 36                                // words per smem row
#define STAGE_BYTES ((GBM + GBN) * G_LDSH * 2)   // 36,864 B
#define G_STAGES 3
#define G_SMEM (G_STAGES * STAGE_BYTES)          // 110,592 B

template<bool HALF_OUT>
__global__ void __launch_bounds__(128, 2) gemm_h_kernel(
    const __half* __restrict__ A, const __half* __restrict__ B,
    void* __restrict__ Cv, const float* __restrict__ bias,
    int M, int N, int K)
{
    extern __shared__ char smem[];

    const int n0 = blockIdx.x * GBN;     // N fastest -> weights L2-resident
    const int m0 = blockIdx.y * GBM;

    const int tid  = threadIdx.x;
    const int warp = tid >> 5;
    const int lane = tid & 31;
    const int wm   = warp >> 1;          // 0..1 -> rows wm*64
    const int wn   = warp & 1;           // 0..1 -> cols wn*64
    const int g    = lane >> 2;          // 0..7
    const int t    = lane & 3;           // 0..3

    float acc[4][8][4];
    #pragma unroll
    for (int i = 0; i < 4; i++)
        #pragma unroll
        for (int j = 0; j < 8; j++)
            #pragma unroll
            for (int c = 0; c < 4; c++)
                acc[i][j][c] = 0.0f;

    const int NB = K / GBK;              // 12

    // stage loader: 256 rows x 8 chunks(16B) = 2048, 16 per thread
    auto issue_stage = [&](int kb, int s) {
        char* dst = smem + s * STAGE_BYTES;
        #pragma unroll
        for (int i = 0; i < 16; i++) {
            int id = tid + i * 128;              // 0..2047
            int r  = id >> 3;                    // 0..255
            int c  = id & 7;                     // 0..7 (8 halves each)
            const __half* gp = (r < GBM)
                ? A + (size_t)(m0 + r) * K + kb * GBK + c * 8
                : B + (size_t)(n0 + r - GBM) * K + kb * GBK + c * 8;
            uint32_t sa = (uint32_t)__cvta_generic_to_shared(dst + r * (G_LDSH * 2) + c * 16);
            cp_async16(sa, gp);
        }
    };

    // fragment loaders; ks = k16-step within stage (0..3)
    auto load_a = [&](const uint32_t* As, int ks, uint32_t a[4][4]) {
        #pragma unroll
        for (int mf = 0; mf < 4; mf++) {
            int w = (wm * 64 + mf * 16 + g) * G_LDSW + ks * 8 + t;
            a[mf][0] = As[w];
            a[mf][1] = As[w + 8 * G_LDSW];
            a[mf][2] = As[w + 4];
            a[mf][3] = As[w + 8 * G_LDSW + 4];
        }
    };
    auto load_b = [&](const uint32_t* Bs, int ks, uint32_t b[8][2]) {
        #pragma unroll
        for (int nf = 0; nf < 8; nf++) {
            int w = (wn * 64 + nf * 8 + g) * G_LDSW + ks * 8 + t;
            b[nf][0] = Bs[w];
            b[nf][1] = Bs[w + 4];
        }
    };

    issue_stage(0, 0); cp_commit();
    issue_stage(1, 1); cp_commit();

    for (int kb = 0; kb < NB; kb++) {
        cp_wait1();            // stage kb resident
        __syncthreads();

        if (kb + 2 < NB) issue_stage(kb + 2, (kb + 2) % 3);
        cp_commit();           // one group per iteration

        const uint32_t* As = (const uint32_t*)(smem + (kb % 3) * STAGE_BYTES);
        const uint32_t* Bs = As + GBM * G_LDSW;

        uint32_t a0[4][4], b0[8][2], a1[4][4], b1[8][2];
        load_a(As, 0, a0); load_b(Bs, 0, b0);

        #pragma unroll
        for (int ks = 0; ks < 4; ks += 2) {
            if (ks + 1 < 4) { load_a(As, ks + 1, a1); load_b(Bs, ks + 1, b1); }
            #pragma unroll
            for (int mf = 0; mf < 4; mf++)
                #pragma unroll
                for (int nf = 0; nf < 8; nf++)
                    mma16816(acc[mf][nf], a0[mf], b0[nf]);
            if (ks + 2 < 4) { load_a(As, ks + 2, a0); load_b(Bs, ks + 2, b0); }
            if (ks + 1 < 4) {
                #pragma unroll
                for (int mf = 0; mf < 4; mf++)
                    #pragma unroll
                    for (int nf = 0; nf < 8; nf++)
                        mma16816(acc[mf][nf], a1[mf], b1[nf]);
            }
        }
        __syncthreads();       // reads of slot kb%3 done before its refill
    }

    // epilogue: fused bias; half2 or float2 stores
    #pragma unroll
    for (int nf = 0; nf < 8; nf++) {
        int col = n0 + wn * 64 + nf * 8 + 2 * t;
        float bx = 0.0f, by = 0.0f;
        if (bias) { float2 bv = *(const float2*)&bias[col]; bx = bv.x; by = bv.y; }
        #pragma unroll
        for (int mf = 0; mf < 4; mf++) {
            int row = m0 + wm * 64 + mf * 16 + g;
            if (HALF_OUT) {
                __half* Ch = (__half*)Cv;
                *(__half2*)&Ch[(size_t)row * N + col] =
                    __floats2half2_rn(acc[mf][nf][0] + bx, acc[mf][nf][1] + by);
                *(__half2*)&Ch[(size_t)(row + 8) * N + col] =
                    __floats2half2_rn(acc[mf][nf][2] + bx, acc[mf][nf][3] + by);
            } else {
                float* Cf = (float*)Cv;
                *(float2*)&Cf[(size_t)row * N + col] =
                    make_float2(acc[mf][nf][0] + bx, acc[mf][nf][1] + by);
                *(float2*)&Cf[(size_t)(row + 8) * N + col] =
                    make_float2(acc[mf][nf][2] + bx, acc[mf][nf][3] + by);
            }
        }
    }
}

// ---------------------------------------------------------------------------
// fp32 -> fp16 conversion prepass
// ---------------------------------------------------------------------------
__global__ void __launch_bounds__(256) f2h_kernel(
    const float* __restrict__ in, __half* __restrict__ out, size_t n4)
{
    size_t i = (size_t)blockIdx.x * 256 + threadIdx.x;
    if (i < n4) {
        float4 v = ((const float4*)in)[i];
        ((__half2*)out)[2 * i + 0] = __floats2half2_rn(v.x, v.y);
        ((__half2*)out)[2 * i + 1] = __floats2half2_rn(v.z, v.w);
    }
}

// ---------------------------------------------------------------------------
// FP16 MMA causal attention per (b,h,n): T=64, hd=64.
// 128 threads = 4 warps; warp w owns query rows 16w..16w+15.
// ---------------------------------------------------------------------------
#define ALDH 72                       // halves per smem row
#define ALDW 36                       // words per row
#define ATTN_SMEM (3 * 64 * ALDH * 2) // 27,648 B

__global__ void __launch_bounds__(128) attn_mma_kernel(
    const __half* __restrict__ qkv, __half* __restrict__ att)
{
    extern __shared__ char smc[];
    __half* sQ  = (__half*)smc;              // [q][d]; reused as sP [q][j]
    __half* sK  = sQ + 64 * ALDH;            // [key][d]
    __half* sVt = sQ + 2 * 64 * ALDH;        // [d][key]

    const int blk = blockIdx.x;
    const int n = blk % NSPAT;
    const int h = (blk / NSPAT) % HEADS;
    const int b = blk / (NSPAT * HEADS);

    const int tid  = threadIdx.x;
    const int warp = tid >> 5;
    const int lane = tid & 31;
    const int g    = lane >> 2;
    const int t    = lane & 3;

    const size_t rowstride = (size_t)NSPAT * QKV_N;
    const size_t base = ((size_t)b * T_SEQ * NSPAT + n) * QKV_N + (size_t)h * HD;

    for (int idx = tid; idx < 64 * 32; idx += 128) {
        int tt = idx >> 5;               // token 0..63
        int d2 = idx & 31;               // half2 index 0..31
        const __half2* gp = (const __half2*)(qkv + base + (size_t)tt * rowstride);
        __half2 q2 = gp[d2];
        __half2 k2 = ((const __half2*)(qkv + base + (size_t)tt * rowstride + CDIM))[d2];
        __half2 v2 = ((const __half2*)(qkv + base + (size_t)tt * rowstride + 2 * CDIM))[d2];
        *(__half2*)&sQ[tt * ALDH + 2 * d2] = q2;
        *(__half2*)&sK[tt * ALDH + 2 * d2] = k2;
        sVt[(2 * d2 + 0) * ALDH + tt] = __low2half(v2);
        sVt[(2 * d2 + 1) * ALDH + tt] = __high2half(v2);
    }
    __syncthreads();

    const int m0 = warp * 16;
    const int i0 = m0 + g;
    const int i1 = m0 + g + 8;

    float s[8][4];
    #pragma unroll
    for (int nf = 0; nf < 8; nf++)
        #pragma unroll
        for (int c = 0; c < 4; c++) s[nf][c] = 0.0f;

    {
        const uint32_t* Qw = (const uint32_t*)sQ;
        const uint32_t* Kw = (const uint32_t*)sK;
        #pragma unroll
        for (int ks = 0; ks < 4; ks++) {
            uint32_t a[4];
            int w = i0 * ALDW + ks * 8 + t;
            a[0] = Qw[w];
            a[1] = Qw[w + 8 * ALDW];
            a[2] = Qw[w + 4];
            a[3] = Qw[w + 8 * ALDW + 4];
            #pragma unroll
            for (int nf = 0; nf < 8; nf++) {
                uint32_t bb[2];
                int wb = (nf * 8 + g) * ALDW + ks * 8 + t;
                bb[0] = Kw[wb];
                bb[1] = Kw[wb + 4];
                mma16816(s[nf], a, bb);
            }
        }
    }

    const float scale = 0.125f;
    float mx0 = -1e30f, mx1 = -1e30f;
    #pragma unroll
    for (int nf = 0; nf < 8; nf++) {
        int j0 = nf * 8 + 2 * t, j1 = j0 + 1;
        s[nf][0] = (j0 <= i0) ? s[nf][0] * scale : -1e30f;
        s[nf][1] = (j1 <= i0) ? s[nf][1] * scale : -1e30f;
        s[nf][2] = (j0 <= i1) ? s[nf][2] * scale : -1e30f;
        s[nf][3] = (j1 <= i1) ? s[nf][3] * scale : -1e30f;
        mx0 = fmaxf(mx0, fmaxf(s[nf][0], s[nf][1]));
        mx1 = fmaxf(mx1, fmaxf(s[nf][2], s[nf][3]));
    }
    mx0 = fmaxf(mx0, __shfl_xor_sync(0xffffffffu, mx0, 1));
    mx0 = fmaxf(mx0, __shfl_xor_sync(0xffffffffu, mx0, 2));
    mx1 = fmaxf(mx1, __shfl_xor_sync(0xffffffffu, mx1, 1));
    mx1 = fmaxf(mx1, __shfl_xor_sync(0xffffffffu, mx1, 2));

    float sum0 = 0.0f, sum1 = 0.0f;
    #pragma unroll
    for (int nf = 0; nf < 8; nf++) {
        s[nf][0] = __expf(s[nf][0] - mx0);
        s[nf][1] = __expf(s[nf][1] - mx0);
        s[nf][2] = __expf(s[nf][2] - mx1);
        s[nf][3] = __expf(s[nf][3] - mx1);
        sum0 += s[nf][0] + s[nf][1];
        sum1 += s[nf][2] + s[nf][3];
    }
    sum0 += __shfl_xor_sync(0xffffffffu, sum0, 1);
    sum0 += __shfl_xor_sync(0xffffffffu, sum0, 2);
    sum1 += __shfl_xor_sync(0xffffffffu, sum1, 1);
    sum1 += __shfl_xor_sync(0xffffffffu, sum1, 2);
    const float inv0 = 1.0f / sum0;
    const float inv1 = 1.0f / sum1;

    __syncwarp();
    __half* sP = sQ;
    #pragma unroll
    for (int nf = 0; nf < 8; nf++) {
        int jc = nf * 8 + 2 * t;
        *(__half2*)&sP[i0 * ALDH + jc] = __floats2half2_rn(s[nf][0] * inv0, s[nf][1] * inv0);
        *(__half2*)&sP[i1 * ALDH + jc] = __floats2half2_rn(s[nf][2] * inv1, s[nf][3] * inv1);
    }
    __syncwarp();

    float o[8][4];
    #pragma unroll
    for (int nf = 0; nf < 8; nf++)
        #pragma unroll
        for (int c = 0; c < 4; c++) o[nf][c] = 0.0f;

    {
        const uint32_t* Pw = (const uint32_t*)sP;
        const uint32_t* Vw = (const uint32_t*)sVt;
        #pragma unroll
        for (int ks = 0; ks < 4; ks++) {
            uint32_t a[4];
            int w = i0 * ALDW + ks * 8 + t;
            a[0] = Pw[w];
            a[1] = Pw[w + 8 * ALDW];
            a[2] = Pw[w + 4];
            a[3] = Pw[w + 8 * ALDW + 4];
            #pragma unroll
            for (int nf = 0; nf < 8; nf++) {
                uint32_t bb[2];
                int wb = (nf * 8 + g) * ALDW + ks * 8 + t;
                bb[0] = Vw[wb];
                bb[1] = Vw[wb + 4];
                mma16816(o[nf], a, bb);
            }
        }
    }

    #pragma unroll
    for (int nf = 0; nf < 8; nf++) {
        int col = nf * 8 + 2 * t;
        size_t a0 = (((size_t)b * T_SEQ + i0) * NSPAT + n) * CDIM + (size_t)h * HD + col;
        size_t a1 = (((size_t)b * T_SEQ + i1) * NSPAT + n) * CDIM + (size_t)h * HD + col;
        *(__half2*)&att[a0] = __floats2half2_rn(o[nf][0], o[nf][1]);
        *(__half2*)&att[a1] = __floats2half2_rn(o[nf][2], o[nf][3]);
    }
}

// ---------------------------------------------------------------------------
extern "C" void kernel_launch(void* const* d_in, const int* in_sizes, int n_in,
                              void* d_out, int out_size)
{
    const float* x      = (const float*)d_in[0];
    const float* w_qkv  = (const float*)d_in[1];
    const float* w_proj = (const float*)d_in[2];
    const float* b_proj = (const float*)d_in[3];
    float* out = (float*)d_out;

    __half *qkv_buf, *att_buf, *xh, *wqh, *wph;
    cudaGetSymbolAddress((void**)&qkv_buf, g_qkv);
    cudaGetSymbolAddress((void**)&att_buf, g_att);
    cudaGetSymbolAddress((void**)&xh, g_xh);
    cudaGetSymbolAddress((void**)&wqh, g_wqh);
    cudaGetSymbolAddress((void**)&wph, g_wph);

    static bool attr_done = false;
    if (!attr_done) {
        cudaFuncSetAttribute(gemm_h_kernel<true>,
                             cudaFuncAttributeMaxDynamicSharedMemorySize, G_SMEM);
        cudaFuncSetAttribute(gemm_h_kernel<false>,
                             cudaFuncAttributeMaxDynamicSharedMemorySize, G_SMEM);
        cudaFuncSetAttribute(attn_mma_kernel,
                             cudaFuncAttributeMaxDynamicSharedMemorySize, ATTN_SMEM);
        attr_done = true;
    }

    // 0) fp16 conversion prepasses
    {
        size_t n4 = (size_t)M_TOT * CDIM / 4;
        f2h_kernel<<<(unsigned)((n4 + 255) / 256), 256>>>(x, xh, n4);
        size_t wq4 = (size_t)QKV_N * CDIM / 4;
        f2h_kernel<<<(unsigned)((wq4 + 255) / 256), 256>>>(w_qkv, wqh, wq4);
        size_t wp4 = (size_t)CDIM * CDIM / 4;
        f2h_kernel<<<(unsigned)((wp4 + 255) / 256), 256>>>(w_proj, wph, wp4);
    }
    // 1) QKV GEMM (fp16 in, fp16 out): (50176 x 768) @ (2304 x 768)^T
    {
        dim3 grid(QKV_N / GBN, M_TOT / GBM);   // (18, 392)
        gemm_h_kernel<true><<<grid, 128, G_SMEM>>>(xh, wqh, (void*)qkv_buf, nullptr,
                                                   M_TOT, QKV_N, CDIM);
    }
    // 2) Attention (fp16 tensor-core)
    {
        dim3 grid(BATCH * HEADS * NSPAT);      // 9408
        attn_mma_kernel<<<grid, 128, ATTN_SMEM>>>(qkv_buf, att_buf);
    }
    // 3) Projection GEMM + fused bias (fp16 in, fp32 out)
    {
        dim3 grid(CDIM / GBN, M_TOT / GBM);    // (6, 392)
        gemm_h_kernel<false><<<grid, 128, G_SMEM>>>(att_buf, wph, (void*)out, b_proj,
                                                    M_TOT, CDIM, CDIM);
    }
}

// round 11
// speedup vs baseline: 2.1064x; 1.0280x over previous
#include <cuda_runtime.h>
#include <cuda_fp16.h>
#include <cstdint>

#define BATCH   4
#define T_SEQ   64
#define NSPAT   196
#define CDIM    768
#define HEADS   12
#define HD      64
#define M_TOT   (BATCH * T_SEQ * NSPAT)   // 50176
#define QKV_N   (3 * CDIM)                // 2304

// Scratch (device globals: allocation-free per harness rules)
__device__ __half g_qkv[(size_t)M_TOT * QKV_N];  // 231 MB
__device__ __half g_att[(size_t)M_TOT * CDIM];   // 77 MB
__device__ __half g_xh [(size_t)M_TOT * CDIM];   // 77 MB  (fp16 x)
__device__ __half g_wqh[(size_t)QKV_N * CDIM];   // fp16 w_qkv
__device__ __half g_wph[(size_t)CDIM * CDIM];    // fp16 w_proj

// ---------------------------------------------------------------------------
// helpers
// ---------------------------------------------------------------------------
__device__ __forceinline__ void cp_async16(uint32_t saddr, const void* gptr) {
    asm volatile("cp.async.cg.shared.global [%0], [%1], 16;\n" :: "r"(saddr), "l"(gptr));
}
__device__ __forceinline__ void cp_commit() {
    asm volatile("cp.async.commit_group;\n" ::: "memory");
}
__device__ __forceinline__ void cp_wait1() {
    asm volatile("cp.async.wait_group 1;\n" ::: "memory");
}
// D += A*B  (m16n8k16 fp16 inputs, fp32 accum)
__device__ __forceinline__ void mma16816(float* d, const uint32_t* a, const uint32_t* b) {
    asm volatile(
        "mma.sync.aligned.m16n8k16.row.col.f32.f16.f16.f32 "
        "{%0,%1,%2,%3}, {%4,%5,%6,%7}, {%8,%9}, {%0,%1,%2,%3};"
        : "+f"(d[0]), "+f"(d[1]), "+f"(d[2]), "+f"(d[3])
        : "r"(a[0]), "r"(a[1]), "r"(a[2]), "r"(a[3]), "r"(b[0]), "r"(b[1]));
}
// 4x 8x8 b16 matrices from shared
__device__ __forceinline__ void ldmx4(uint32_t& r0, uint32_t& r1, uint32_t& r2, uint32_t& r3,
                                      uint32_t saddr) {
    asm volatile("ldmatrix.sync.aligned.m8n8.x4.shared.b16 {%0,%1,%2,%3}, [%4];"
                 : "=r"(r0), "=r"(r1), "=r"(r2), "=r"(r3) : "r"(saddr));
}

// ---------------------------------------------------------------------------
// FP16 MMA GEMM: C[m][n] = sum_k A[m*K+k] * B[n*K+k] (+ bias[n])
// Block 128(m) x 128(n), BK=64, 3-stage cp.async, 128 threads = 4 warps (2x2),
// warp tile 64x64; fragments via ldmatrix.x4, double-buffered.
// 2 CTAs co-resident per SM.
// ---------------------------------------------------------------------------
#define GBM 128
#define GBN 128
#define GBK 64
#define G_ROWB 144                               // bytes per smem row
#define STAGE_BYTES ((GBM + GBN) * G_ROWB)       // 36,864 B
#define G_STAGES 3
#define G_SMEM (G_STAGES * STAGE_BYTES)          // 110,592 B

template<bool HALF_OUT>
__global__ void __launch_bounds__(128, 2) gemm_h_kernel(
    const __half* __restrict__ A, const __half* __restrict__ B,
    void* __restrict__ Cv, const float* __restrict__ bias,
    int M, int N, int K)
{
    extern __shared__ char smem[];
    const uint32_t sbase = (uint32_t)__cvta_generic_to_shared(smem);

    const int n0 = blockIdx.x * GBN;     // N fastest -> weights L2-resident
    const int m0 = blockIdx.y * GBM;

    const int tid  = threadIdx.x;
    const int warp = tid >> 5;
    const int lane = tid & 31;
    const int wm   = warp >> 1;          // 0..1 -> rows wm*64
    const int wn   = warp & 1;           // 0..1 -> cols wn*64
    const int g    = lane >> 2;          // 0..7
    const int t    = lane & 3;           // 0..3
    const int quad = lane >> 3;          // 0..3 (ldmatrix address group)
    const int qr   = lane & 7;           // row within group

    // per-thread intra-stage ldmatrix offsets
    // A: matrices [rows, rows+8] x [k lo16B, k hi16B]
    const uint32_t a_off = (uint32_t)((wm * 64 + (quad & 1) * 8 + qr) * G_ROWB
                                      + (quad >> 1) * 16);
    // B: matrices [nblk, nblk+8] x [k lo16B, k hi16B] -> regs b[2p][0],b[2p][1],b[2p+1][0],b[2p+1][1]
    const uint32_t b_off = (uint32_t)(GBM * G_ROWB
                                      + (wn * 64 + (quad >> 1) * 8 + qr) * G_ROWB
                                      + (quad & 1) * 16);

    float acc[4][8][4];
    #pragma unroll
    for (int i = 0; i < 4; i++)
        #pragma unroll
        for (int j = 0; j < 8; j++)
            #pragma unroll
            for (int c = 0; c < 4; c++)
                acc[i][j][c] = 0.0f;

    const int NB = K / GBK;              // 12

    // stage loader: 256 rows x 8 chunks(16B) = 2048, 16 per thread
    auto issue_stage = [&](int kb, int s) {
        char* dst = smem + s * STAGE_BYTES;
        #pragma unroll
        for (int i = 0; i < 16; i++) {
            int id = tid + i * 128;              // 0..2047
            int r  = id >> 3;                    // 0..255
            int c  = id & 7;                     // 0..7 (8 halves each)
            const __half* gp = (r < GBM)
                ? A + (size_t)(m0 + r) * K + kb * GBK + c * 8
                : B + (size_t)(n0 + r - GBM) * K + kb * GBK + c * 8;
            uint32_t sa = (uint32_t)__cvta_generic_to_shared(dst + r * G_ROWB + c * 16);
            cp_async16(sa, gp);
        }
    };

    auto load_a = [&](uint32_t stg, int ks, uint32_t a[4][4]) {
        #pragma unroll
        for (int mf = 0; mf < 4; mf++)
            ldmx4(a[mf][0], a[mf][1], a[mf][2], a[mf][3],
                  stg + a_off + (uint32_t)(mf * 16 * G_ROWB + ks * 32));
    };
    auto load_b = [&](uint32_t stg, int ks, uint32_t b[8][2]) {
        #pragma unroll
        for (int p = 0; p < 4; p++)
            ldmx4(b[2 * p][0], b[2 * p][1], b[2 * p + 1][0], b[2 * p + 1][1],
                  stg + b_off + (uint32_t)(p * 16 * G_ROWB + ks * 32));
    };

    issue_stage(0, 0); cp_commit();
    issue_stage(1, 1); cp_commit();

    for (int kb = 0; kb < NB; kb++) {
        cp_wait1();            // stage kb resident
        __syncthreads();

        if (kb + 2 < NB) issue_stage(kb + 2, (kb + 2) % 3);
        cp_commit();           // one group per iteration

        const uint32_t stg = sbase + (uint32_t)((kb % 3) * STAGE_BYTES);

        uint32_t a0[4][4], b0[8][2], a1[4][4], b1[8][2];
        load_a(stg, 0, a0); load_b(stg, 0, b0);

        #pragma unroll
        for (int ks = 0; ks < 4; ks += 2) {
            if (ks + 1 < 4) { load_a(stg, ks + 1, a1); load_b(stg, ks + 1, b1); }
            #pragma unroll
            for (int mf = 0; mf < 4; mf++)
                #pragma unroll
                for (int nf = 0; nf < 8; nf++)
                    mma16816(acc[mf][nf], a0[mf], b0[nf]);
            if (ks + 2 < 4) { load_a(stg, ks + 2, a0); load_b(stg, ks + 2, b0); }
            if (ks + 1 < 4) {
                #pragma unroll
                for (int mf = 0; mf < 4; mf++)
                    #pragma unroll
                    for (int nf = 0; nf < 8; nf++)
                        mma16816(acc[mf][nf], a1[mf], b1[nf]);
            }
        }
        __syncthreads();       // reads of slot kb%3 done before its refill
    }

    // epilogue: fused bias; half2 or float2 stores
    #pragma unroll
    for (int nf = 0; nf < 8; nf++) {
        int col = n0 + wn * 64 + nf * 8 + 2 * t;
        float bx = 0.0f, by = 0.0f;
        if (bias) { float2 bv = *(const float2*)&bias[col]; bx = bv.x; by = bv.y; }
        #pragma unroll
        for (int mf = 0; mf < 4; mf++) {
            int row = m0 + wm * 64 + mf * 16 + g;
            if (HALF_OUT) {
                __half* Ch = (__half*)Cv;
                *(__half2*)&Ch[(size_t)row * N + col] =
                    __floats2half2_rn(acc[mf][nf][0] + bx, acc[mf][nf][1] + by);
                *(__half2*)&Ch[(size_t)(row + 8) * N + col] =
                    __floats2half2_rn(acc[mf][nf][2] + bx, acc[mf][nf][3] + by);
            } else {
                float* Cf = (float*)Cv;
                *(float2*)&Cf[(size_t)row * N + col] =
                    make_float2(acc[mf][nf][0] + bx, acc[mf][nf][1] + by);
                *(float2*)&Cf[(size_t)(row + 8) * N + col] =
                    make_float2(acc[mf][nf][2] + bx, acc[mf][nf][3] + by);
            }
        }
    }
}

// ---------------------------------------------------------------------------
// fp32 -> fp16 conversion prepass
// ---------------------------------------------------------------------------
__global__ void __launch_bounds__(256) f2h_kernel(
    const float* __restrict__ in, __half* __restrict__ out, size_t n4)
{
    size_t i = (size_t)blockIdx.x * 256 + threadIdx.x;
    if (i < n4) {
        float4 v = ((const float4*)in)[i];
        ((__half2*)out)[2 * i + 0] = __floats2half2_rn(v.x, v.y);
        ((__half2*)out)[2 * i + 1] = __floats2half2_rn(v.z, v.w);
    }
}

// ---------------------------------------------------------------------------
// FP16 MMA causal attention per (b,h,n): T=64, hd=64.
// 128 threads = 4 warps; warp w owns query rows 16w..16w+15.
// ---------------------------------------------------------------------------
#define ALDH 72                       // halves per smem row
#define ALDW 36                       // words per row
#define ATTN_SMEM (3 * 64 * ALDH * 2) // 27,648 B

__global__ void __launch_bounds__(128) attn_mma_kernel(
    const __half* __restrict__ qkv, __half* __restrict__ att)
{
    extern __shared__ char smc[];
    __half* sQ  = (__half*)smc;              // [q][d]; reused as sP [q][j]
    __half* sK  = sQ + 64 * ALDH;            // [key][d]
    __half* sVt = sQ + 2 * 64 * ALDH;        // [d][key]

    const int blk = blockIdx.x;
    const int n = blk % NSPAT;
    const int h = (blk / NSPAT) % HEADS;
    const int b = blk / (NSPAT * HEADS);

    const int tid  = threadIdx.x;
    const int warp = tid >> 5;
    const int lane = tid & 31;
    const int g    = lane >> 2;
    const int t    = lane & 3;

    const size_t rowstride = (size_t)NSPAT * QKV_N;
    const size_t base = ((size_t)b * T_SEQ * NSPAT + n) * QKV_N + (size_t)h * HD;

    for (int idx = tid; idx < 64 * 32; idx += 128) {
        int tt = idx >> 5;               // token 0..63
        int d2 = idx & 31;               // half2 index 0..31
        const __half2* gp = (const __half2*)(qkv + base + (size_t)tt * rowstride);
        __half2 q2 = gp[d2];
        __half2 k2 = ((const __half2*)(qkv + base + (size_t)tt * rowstride + CDIM))[d2];
        __half2 v2 = ((const __half2*)(qkv + base + (size_t)tt * rowstride + 2 * CDIM))[d2];
        *(__half2*)&sQ[tt * ALDH + 2 * d2] = q2;
        *(__half2*)&sK[tt * ALDH + 2 * d2] = k2;
        sVt[(2 * d2 + 0) * ALDH + tt] = __low2half(v2);
        sVt[(2 * d2 + 1) * ALDH + tt] = __high2half(v2);
    }
    __syncthreads();

    const int m0 = warp * 16;
    const int i0 = m0 + g;
    const int i1 = m0 + g + 8;

    float s[8][4];
    #pragma unroll
    for (int nf = 0; nf < 8; nf++)
        #pragma unroll
        for (int c = 0; c < 4; c++) s[nf][c] = 0.0f;

    {
        const uint32_t* Qw = (const uint32_t*)sQ;
        const uint32_t* Kw = (const uint32_t*)sK;
        #pragma unroll
        for (int ks = 0; ks < 4; ks++) {
            uint32_t a[4];
            int w = i0 * ALDW + ks * 8 + t;
            a[0] = Qw[w];
            a[1] = Qw[w + 8 * ALDW];
            a[2] = Qw[w + 4];
            a[3] = Qw[w + 8 * ALDW + 4];
            #pragma unroll
            for (int nf = 0; nf < 8; nf++) {
                uint32_t bb[2];
                int wb = (nf * 8 + g) * ALDW + ks * 8 + t;
                bb[0] = Kw[wb];
                bb[1] = Kw[wb + 4];
                mma16816(s[nf], a, bb);
            }
        }
    }

    const float scale = 0.125f;
    float mx0 = -1e30f, mx1 = -1e30f;
    #pragma unroll
    for (int nf = 0; nf < 8; nf++) {
        int j0 = nf * 8 + 2 * t, j1 = j0 + 1;
        s[nf][0] = (j0 <= i0) ? s[nf][0] * scale : -1e30f;
        s[nf][1] = (j1 <= i0) ? s[nf][1] * scale : -1e30f;
        s[nf][2] = (j0 <= i1) ? s[nf][2] * scale : -1e30f;
        s[nf][3] = (j1 <= i1) ? s[nf][3] * scale : -1e30f;
        mx0 = fmaxf(mx0, fmaxf(s[nf][0], s[nf][1]));
        mx1 = fmaxf(mx1, fmaxf(s[nf][2], s[nf][3]));
    }
    mx0 = fmaxf(mx0, __shfl_xor_sync(0xffffffffu, mx0, 1));
    mx0 = fmaxf(mx0, __shfl_xor_sync(0xffffffffu, mx0, 2));
    mx1 = fmaxf(mx1, __shfl_xor_sync(0xffffffffu, mx1, 1));
    mx1 = fmaxf(mx1, __shfl_xor_sync(0xffffffffu, mx1, 2));

    float sum0 = 0.0f, sum1 = 0.0f;
    #pragma unroll
    for (int nf = 0; nf < 8; nf++) {
        s[nf][0] = __expf(s[nf][0] - mx0);
        s[nf][1] = __expf(s[nf][1] - mx0);
        s[nf][2] = __expf(s[nf][2] - mx1);
        s[nf][3] = __expf(s[nf][3] - mx1);
        sum0 += s[nf][0] + s[nf][1];
        sum1 += s[nf][2] + s[nf][3];
    }
    sum0 += __shfl_xor_sync(0xffffffffu, sum0, 1);
    sum0 += __shfl_xor_sync(0xffffffffu, sum0, 2);
    sum1 += __shfl_xor_sync(0xffffffffu, sum1, 1);
    sum1 += __shfl_xor_sync(0xffffffffu, sum1, 2);
    const float inv0 = 1.0f / sum0;
    const float inv1 = 1.0f / sum1;

    __syncwarp();
    __half* sP = sQ;
    #pragma unroll
    for (int nf = 0; nf < 8; nf++) {
        int jc = nf * 8 + 2 * t;
        *(__half2*)&sP[i0 * ALDH + jc] = __floats2half2_rn(s[nf][0] * inv0, s[nf][1] * inv0);
        *(__half2*)&sP[i1 * ALDH + jc] = __floats2half2_rn(s[nf][2] * inv1, s[nf][3] * inv1);
    }
    __syncwarp();

    float o[8][4];
    #pragma unroll
    for (int nf = 0; nf < 8; nf++)
        #pragma unroll
        for (int c = 0; c < 4; c++) o[nf][c] = 0.0f;

    {
        const uint32_t* Pw = (const uint32_t*)sP;
        const uint32_t* Vw = (const uint32_t*)sVt;
        #pragma unroll
        for (int ks = 0; ks < 4; ks++) {
            uint32_t a[4];
            int w = i0 * ALDW + ks * 8 + t;
            a[0] = Pw[w];
            a[1] = Pw[w + 8 * ALDW];
            a[2] = Pw[w + 4];
            a[3] = Pw[w + 8 * ALDW + 4];
            #pragma unroll
            for (int nf = 0; nf < 8; nf++) {
                uint32_t bb[2];
                int wb = (nf * 8 + g) * ALDW + ks * 8 + t;
                bb[0] = Vw[wb];
                bb[1] = Vw[wb + 4];
                mma16816(o[nf], a, bb);
            }
        }
    }

    #pragma unroll
    for (int nf = 0; nf < 8; nf++) {
        int col = nf * 8 + 2 * t;
        size_t a0 = (((size_t)b * T_SEQ + i0) * NSPAT + n) * CDIM + (size_t)h * HD + col;
        size_t a1 = (((size_t)b * T_SEQ + i1) * NSPAT + n) * CDIM + (size_t)h * HD + col;
        *(__half2*)&att[a0] = __floats2half2_rn(o[nf][0], o[nf][1]);
        *(__half2*)&att[a1] = __floats2half2_rn(o[nf][2], o[nf][3]);
    }
}

// ---------------------------------------------------------------------------
extern "C" void kernel_launch(void* const* d_in, const int* in_sizes, int n_in,
                              void* d_out, int out_size)
{
    const float* x      = (const float*)d_in[0];
    const float* w_qkv  = (const float*)d_in[1];
    const float* w_proj = (const float*)d_in[2];
    const float* b_proj = (const float*)d_in[3];
    float* out = (float*)d_out;

    __half *qkv_buf, *att_buf, *xh, *wqh, *wph;
    cudaGetSymbolAddress((void**)&qkv_buf, g_qkv);
    cudaGetSymbolAddress((void**)&att_buf, g_att);
    cudaGetSymbolAddress((void**)&xh, g_xh);
    cudaGetSymbolAddress((void**)&wqh, g_wqh);
    cudaGetSymbolAddress((void**)&wph, g_wph);

    static bool attr_done = false;
    if (!attr_done) {
        cudaFuncSetAttribute(gemm_h_kernel<true>,
                             cudaFuncAttributeMaxDynamicSharedMemorySize, G_SMEM);
        cudaFuncSetAttribute(gemm_h_kernel<false>,
                             cudaFuncAttributeMaxDynamicSharedMemorySize, G_SMEM);
        cudaFuncSetAttribute(attn_mma_kernel,
                             cudaFuncAttributeMaxDynamicSharedMemorySize, ATTN_SMEM);
        attr_done = true;
    }

    // 0) fp16 conversion prepasses
    {
        size_t n4 = (size_t)M_TOT * CDIM / 4;
        f2h_kernel<<<(unsigned)((n4 + 255) / 256), 256>>>(x, xh, n4);
        size_t wq4 = (size_t)QKV_N * CDIM / 4;
        f2h_kernel<<<(unsigned)((wq4 + 255) / 256), 256>>>(w_qkv, wqh, wq4);
        size_t wp4 = (size_t)CDIM * CDIM / 4;
        f2h_kernel<<<(unsigned)((wp4 + 255) / 256), 256>>>(w_proj, wph, wp4);
    }
    // 1) QKV GEMM (fp16 in, fp16 out): (50176 x 768) @ (2304 x 768)^T
    {
        dim3 grid(QKV_N / GBN, M_TOT / GBM);   // (18, 392)
        gemm_h_kernel<true><<<grid, 128, G_SMEM>>>(xh, wqh, (void*)qkv_buf, nullptr,
                                                   M_TOT, QKV_N, CDIM);
    }
    // 2) Attention (fp16 tensor-core)
    {
        dim3 grid(BATCH * HEADS * NSPAT);      // 9408
        attn_mma_kernel<<<grid, 128, ATTN_SMEM>>>(qkv_buf, att_buf);
    }
    // 3) Projection GEMM + fused bias (fp16 in, fp32 out)
    {
        dim3 grid(CDIM / GBN, M_TOT / GBM);    // (6, 392)
        gemm_h_kernel<false><<<grid, 128, G_SMEM>>>(att_buf, wph, (void*)out, b_proj,
                                                    M_TOT, CDIM, CDIM);
    }
}